// round 8
// baseline (speedup 1.0000x reference)
#include <cuda_runtime.h>
#include <cuda_bf16.h>
#include <cuda_fp16.h>
#include <cstdint>

#define B_   16
#define V_   20000
#define D_   256
#define H_   256
#define EPS_ 1e-5f

// ======================= helpers =======================
__device__ __forceinline__ uint32_t smem_u32(const void* p) {
    uint32_t a;
    asm("{ .reg .u64 t; cvta.to.shared.u64 t, %1; cvt.u32.u64 %0, t; }" : "=r"(a) : "l"(p));
    return a;
}
__device__ __forceinline__ void ldsm4(uint32_t* r, uint32_t addr) {
    asm volatile("ldmatrix.sync.aligned.m8n8.x4.shared.b16 {%0,%1,%2,%3}, [%4];"
        : "=r"(r[0]), "=r"(r[1]), "=r"(r[2]), "=r"(r[3]) : "r"(addr));
}
__device__ __forceinline__ void ldsm4t(uint32_t* r, uint32_t addr) {
    asm volatile("ldmatrix.sync.aligned.m8n8.x4.trans.shared.b16 {%0,%1,%2,%3}, [%4];"
        : "=r"(r[0]), "=r"(r[1]), "=r"(r[2]), "=r"(r[3]) : "r"(addr));
}
__device__ __forceinline__ void mma_bf16(float* c, const uint32_t* a, const uint32_t* b) {
    asm volatile("mma.sync.aligned.m16n8k16.row.col.f32.bf16.bf16.f32 "
        "{%0,%1,%2,%3}, {%4,%5,%6,%7}, {%8,%9}, {%0,%1,%2,%3};"
        : "+f"(c[0]), "+f"(c[1]), "+f"(c[2]), "+f"(c[3])
        : "r"(a[0]), "r"(a[1]), "r"(a[2]), "r"(a[3]), "r"(b[0]), "r"(b[1]));
}
__device__ __forceinline__ void mma_f16(float* c, uint32_t a0, uint32_t a1, uint32_t a2, uint32_t a3,
                                        uint32_t b0, uint32_t b1) {
    asm volatile("mma.sync.aligned.m16n8k16.row.col.f32.f16.f16.f32 "
        "{%0,%1,%2,%3}, {%4,%5,%6,%7}, {%8,%9}, {%0,%1,%2,%3};"
        : "+f"(c[0]), "+f"(c[1]), "+f"(c[2]), "+f"(c[3])
        : "r"(a0), "r"(a1), "r"(a2), "r"(a3), "r"(b0), "r"(b1));
}
__device__ __forceinline__ uint32_t pack2bf16(float a, float b) {
    unsigned short ua = __bfloat16_as_ushort(__float2bfloat16(a));
    unsigned short ub = __bfloat16_as_ushort(__float2bfloat16(b));
    return ((uint32_t)ub << 16) | ua;
}
__device__ __forceinline__ void cp16(uint32_t dst, const void* src) {
    asm volatile("cp.async.cg.shared.global [%0], [%1], 16;" :: "r"(dst), "l"(src));
}
#define CP_COMMIT() asm volatile("cp.async.commit_group;" ::: "memory")
#define CP_WAIT(n)  asm volatile("cp.async.wait_group %0;" :: "n"(n) : "memory")

// ======================= scratch =======================
__device__ float g_pht[H_ * B_];          // [h][b]
__device__ float g_ah[V_ * D_];
__device__ float g_scores[B_ * V_];
// split weights, NO transpose: [mat(2)][split(2)][k(256)][n(256)] bf16
__device__ __align__(16) __nv_bfloat16 g_Bs[2 * 2 * 256 * 256];

// ---------------- prep (blocks 0..31) + patient (blocks 32..47) ----------------
__global__ void k_prep(const float* __restrict__ Wa, const float* __restrict__ W1,
                       const float* __restrict__ pe, const float* __restrict__ Wp,
                       const float* __restrict__ bp, const float* __restrict__ gp,
                       const float* __restrict__ betap, const float* __restrict__ b1)
{
    if (blockIdx.x < 32) {
        int mat = blockIdx.x >> 4;
        int kg  = blockIdx.x & 15;
        int n   = threadIdx.x;
        const float* W = mat ? (W1 + (size_t)D_ * H_) : Wa;   // [k][n]
        __nv_bfloat16* dh = g_Bs + (size_t)(mat * 2 + 0) * 65536;
        __nv_bfloat16* dl = g_Bs + (size_t)(mat * 2 + 1) * 65536;
        #pragma unroll 4
        for (int kp = 0; kp < 16; kp++) {
            int k = kg * 16 + kp;
            float v = W[(size_t)k * 256 + n];
            __nv_bfloat16 h = __float2bfloat16(v);
            dh[(size_t)k * 256 + n] = h;
            dl[(size_t)k * 256 + n] = __float2bfloat16(v - __bfloat162float(h));
        }
        return;
    }
    int b = blockIdx.x - 32, d = threadIdx.x;
    __shared__ float s_pe[D_], s_p[D_];
    s_pe[d] = pe[b * D_ + d];
    __syncthreads();
    float acc = bp[d];
    #pragma unroll 8
    for (int k = 0; k < D_; k++) acc = fmaf(s_pe[k], Wp[k * D_ + d], acc);
    float s1 = acc, s2 = acc * acc;
    #pragma unroll
    for (int o = 16; o; o >>= 1) {
        s1 += __shfl_xor_sync(0xffffffffu, s1, o);
        s2 += __shfl_xor_sync(0xffffffffu, s2, o);
    }
    __shared__ float r1[8], r2[8], bc[2];
    int w = d >> 5, l = d & 31;
    if (l == 0) { r1[w] = s1; r2[w] = s2; }
    __syncthreads();
    if (d == 0) {
        float t1 = 0.f, t2 = 0.f;
        #pragma unroll
        for (int i = 0; i < 8; i++) { t1 += r1[i]; t2 += r2[i]; }
        float mean = t1 * (1.0f / D_);
        float var  = t2 * (1.0f / D_) - mean * mean;
        bc[0] = mean; bc[1] = rsqrtf(var + EPS_);
    }
    __syncthreads();
    s_p[d] = (acc - bc[0]) * bc[1] * gp[d] + betap[d];
    __syncthreads();
    float acc2 = b1[d];
    #pragma unroll 8
    for (int k = 0; k < D_; k++) acc2 = fmaf(s_p[k], W1[k * H_ + d], acc2);
    g_pht[d * B_ + b] = acc2;
}

// ---------------- fused HMMA kernel: 3-stage, 1 sync per chunk ----------------
// A: 64 rows x 512B (swizzled), hi + lo.  B slots: 16 k-rows x 1040B
// (hi 512 | lo 512 | pad 16).  Epilogue scratch lives in the dead slot 2.
static constexpr uint32_t A_HI   = 0;
static constexpr uint32_t A_LO   = 32768;
static constexpr uint32_t B_B0   = 65536;
static constexpr uint32_t B_STR  = 16640;     // per stage
static constexpr uint32_t SC_BA  = 98816;     // == B_B0 + 2*B_STR (slot 2)
static constexpr uint32_t SC_GA  = 99840;
static constexpr uint32_t SC_BE  = 100864;
static constexpr uint32_t SC_PS  = 101888;
static constexpr uint32_t SC_PQ  = 102912;
static constexpr uint32_t SC_MR  = 103936;
static constexpr uint32_t SMEM_SZ = 115456;   // 65536 + 3*16640

__global__ __launch_bounds__(256, 2)
void k_fused(const float* __restrict__ atc4,
             const float* __restrict__ ba,
             const float* __restrict__ ga,
             const float* __restrict__ betaa)
{
    extern __shared__ __align__(16) unsigned char smem[];
    uint32_t sb = smem_u32(smem);
    int tid = threadIdx.x;
    int wid = tid >> 5;
    int l   = tid & 31;
    int wm  = wid >> 2;
    int wn  = wid & 3;
    int quad = l >> 2;
    int tid4 = l & 3;
    int m0 = blockIdx.x * 64;

    auto issue = [&](int t) {
        int phase = t >> 4, c = t & 15;
        uint32_t bb = sb + B_B0 + (uint32_t)(t % 3) * B_STR;
        const __nv_bfloat16* bh = g_Bs + (size_t)(phase * 2) * 65536 + (size_t)c * 16 * 256;
        const __nv_bfloat16* bl = bh + 65536;
        #pragma unroll
        for (int it = 0; it < 2; it++) {
            int id = it * 256 + tid;       // 0..511
            int k = id >> 5, u = id & 31;
            uint32_t dst = bb + (uint32_t)k * 1040 + (uint32_t)u * 16;
            cp16(dst,       bh + (size_t)k * 256 + u * 8);
            cp16(dst + 512, bl + (size_t)k * 256 + u * 8);
        }
        CP_COMMIT();
    };

    issue(0);
    issue(1);

    // ---- convert atc4 tile -> bf16 hi/lo into swizzled A smem ----
    #pragma unroll
    for (int it = 0; it < 8; it++) {
        int id = it * 256 + tid;
        int row = id >> 5, u = id & 31;
        int gr = m0 + row;
        float f[8];
        if (gr < V_) {
            float4 v0 = *(const float4*)&atc4[(size_t)gr * 256 + u * 8];
            float4 v1 = *(const float4*)&atc4[(size_t)gr * 256 + u * 8 + 4];
            f[0]=v0.x; f[1]=v0.y; f[2]=v0.z; f[3]=v0.w;
            f[4]=v1.x; f[5]=v1.y; f[6]=v1.z; f[7]=v1.w;
        } else {
            #pragma unroll
            for (int i = 0; i < 8; i++) f[i] = 0.f;
        }
        float hf[8], lf[8];
        #pragma unroll
        for (int i = 0; i < 8; i++) {
            hf[i] = __bfloat162float(__float2bfloat16(f[i]));
            lf[i] = f[i] - hf[i];
        }
        uint4 hp, lp;
        hp.x = pack2bf16(hf[0], hf[1]); hp.y = pack2bf16(hf[2], hf[3]);
        hp.z = pack2bf16(hf[4], hf[5]); hp.w = pack2bf16(hf[6], hf[7]);
        lp.x = pack2bf16(lf[0], lf[1]); lp.y = pack2bf16(lf[2], lf[3]);
        lp.z = pack2bf16(lf[4], lf[5]); lp.w = pack2bf16(lf[6], lf[7]);
        uint32_t off = (uint32_t)row * 512 + (((uint32_t)u ^ ((uint32_t)row & 7)) << 4);
        *(uint4*)(smem + A_HI + off) = hp;
        *(uint4*)(smem + A_LO + off) = lp;
    }

    int ar = wm * 32 + (l & 15);
    uint32_t arx = (uint32_t)(ar & 7);
    uint32_t a_base = sb + A_HI + (uint32_t)ar * 512;
    uint32_t kusel = (uint32_t)((l >> 4) & 1);
    uint32_t b_lane = (uint32_t)(l & 15) * 1040 + (uint32_t)(wn * 64 + ((l >> 4) & 1) * 8) * 2;

    float acc[8][2][4];
    #pragma unroll
    for (int nb = 0; nb < 8; nb++)
        #pragma unroll
        for (int mb = 0; mb < 2; mb++)
            #pragma unroll
            for (int i = 0; i < 4; i++) acc[nb][mb][i] = 0.f;

    #pragma unroll 1
    for (int t = 0; t < 32; t++) {
        int c = t & 15;
        uint32_t bb = sb + B_B0 + (uint32_t)(t % 3) * B_STR;

        if (t == 31) { CP_WAIT(0); } else { CP_WAIT(1); }
        __syncthreads();            // data visible; slot (t+2)%3 fully consumed at t-1
        if (t < 30 && t != 15) issue(t + 2);
        if (t == 15) {
            // stage params into dead slot-2 scratch (chunk 14's old buffer)
            ((float*)(smem + SC_BA))[tid] = ba[tid];
            ((float*)(smem + SC_GA))[tid] = ga[tid];
            ((float*)(smem + SC_BE))[tid] = betaa[tid];
        }

        uint32_t ku = (uint32_t)(c * 2) + kusel;
        uint32_t aa = a_base + ((ku ^ arx) << 4);
        uint32_t ah0[4], ah1[4], al0[4], al1[4];
        ldsm4(ah0, aa);
        ldsm4(ah1, aa + 8192);
        ldsm4(al0, aa + 32768);
        ldsm4(al1, aa + 40960);
        #pragma unroll
        for (int p = 0; p < 4; p++) {
            uint32_t bo = bb + b_lane + (uint32_t)(p * 32);
            uint32_t rh[4], rl[4];
            ldsm4t(rh, bo);
            ldsm4t(rl, bo + 512);
            #pragma unroll
            for (int q = 0; q < 2; q++) {
                int nb = p * 2 + q;
                mma_bf16(acc[nb][0], ah0, &rh[q * 2]);
                mma_bf16(acc[nb][0], ah0, &rl[q * 2]);
                mma_bf16(acc[nb][0], al0, &rh[q * 2]);
                mma_bf16(acc[nb][1], ah1, &rh[q * 2]);
                mma_bf16(acc[nb][1], ah1, &rl[q * 2]);
                mma_bf16(acc[nb][1], al1, &rh[q * 2]);
            }
        }

        if (t == 15) {
            __syncthreads();       // all warps done with chunk 15 + param writes visible
            const float* s_ba = (const float*)(smem + SC_BA);
            const float* s_ga = (const float*)(smem + SC_GA);
            const float* s_be = (const float*)(smem + SC_BE);
            float* psum = (float*)(smem + SC_PS);
            float* psq  = (float*)(smem + SC_PQ);
            float* mrs  = (float*)(smem + SC_MR);

            #pragma unroll
            for (int mb = 0; mb < 2; mb++) {
                #pragma unroll
                for (int half = 0; half < 2; half++) {
                    float s1 = 0.f, s2 = 0.f;
                    #pragma unroll
                    for (int nb = 0; nb < 8; nb++) {
                        int col = wn * 64 + nb * 8 + tid4 * 2;
                        float x0 = acc[nb][mb][half * 2 + 0] + s_ba[col];
                        float x1 = acc[nb][mb][half * 2 + 1] + s_ba[col + 1];
                        s1 += x0 + x1;
                        s2 = fmaf(x0, x0, fmaf(x1, x1, s2));
                    }
                    s1 += __shfl_xor_sync(0xffffffffu, s1, 1);
                    s2 += __shfl_xor_sync(0xffffffffu, s2, 1);
                    s1 += __shfl_xor_sync(0xffffffffu, s1, 2);
                    s2 += __shfl_xor_sync(0xffffffffu, s2, 2);
                    if (tid4 == 0) {
                        int row = wm * 32 + mb * 16 + quad + half * 8;
                        psum[row * 4 + wn] = s1;
                        psq[row * 4 + wn]  = s2;
                    }
                }
            }
            __syncthreads();
            if (tid < 64) {
                float s1 = psum[tid * 4] + psum[tid * 4 + 1] + psum[tid * 4 + 2] + psum[tid * 4 + 3];
                float s2 = psq[tid * 4] + psq[tid * 4 + 1] + psq[tid * 4 + 2] + psq[tid * 4 + 3];
                float mean = s1 * (1.0f / 256.0f);
                float var  = s2 * (1.0f / 256.0f) - mean * mean;
                mrs[tid * 2]     = mean;
                mrs[tid * 2 + 1] = rsqrtf(var + EPS_);
            }
            __syncthreads();
            #pragma unroll
            for (int mb = 0; mb < 2; mb++) {
                #pragma unroll
                for (int half = 0; half < 2; half++) {
                    int row = wm * 32 + mb * 16 + quad + half * 8;
                    float mean = mrs[row * 2], rstd = mrs[row * 2 + 1];
                    #pragma unroll
                    for (int nb = 0; nb < 8; nb++) {
                        int col = wn * 64 + nb * 8 + tid4 * 2;
                        float x0 = acc[nb][mb][half * 2 + 0] + s_ba[col];
                        float x1 = acc[nb][mb][half * 2 + 1] + s_ba[col + 1];
                        float v0 = (x0 - mean) * rstd * s_ga[col] + s_be[col];
                        float v1 = (x1 - mean) * rstd * s_ga[col + 1] + s_be[col + 1];
                        float h0 = __bfloat162float(__float2bfloat16(v0));
                        float h1 = __bfloat162float(__float2bfloat16(v1));
                        uint32_t u = (uint32_t)(col >> 3);
                        uint32_t off = (uint32_t)row * 512 + ((u ^ ((uint32_t)row & 7)) << 4)
                                     + (uint32_t)tid4 * 4;
                        *(uint32_t*)(smem + A_HI + off) = pack2bf16(h0, h1);
                        *(uint32_t*)(smem + A_LO + off) = pack2bf16(v0 - h0, v1 - h1);
                    }
                }
            }
            #pragma unroll
            for (int nb = 0; nb < 8; nb++)
                #pragma unroll
                for (int mb = 0; mb < 2; mb++)
                    #pragma unroll
                    for (int i = 0; i < 4; i++) acc[nb][mb][i] = 0.f;
            __syncthreads();       // scratch dead + A rewritten before issue(17)/chunk 16
            issue(17);             // into slot 2 (scratch area now dead)
        }

        if (t == 31) {
            #pragma unroll
            for (int mb = 0; mb < 2; mb++) {
                #pragma unroll
                for (int half = 0; half < 2; half++) {
                    int row = wm * 32 + mb * 16 + quad + half * 8;
                    int grow = m0 + row;
                    if (grow < V_) {
                        #pragma unroll
                        for (int nb = 0; nb < 8; nb++) {
                            int col = wn * 64 + nb * 8 + tid4 * 2;
                            float2 o = make_float2(acc[nb][mb][half * 2], acc[nb][mb][half * 2 + 1]);
                            *(float2*)&g_ah[(size_t)grow * 256 + col] = o;
                        }
                    }
                }
            }
        }
    }
}

// ---------------- score: tanh f16x2 feeding mma.f16 (tensor pipe is idle here) ----------------
// Per warp: 2 vocab rows; per v: 16 k-steps of m16n8k16 with A=tanh(ah+pht), B=W2 replicated.
__global__ __launch_bounds__(256)
void k_score(const float* __restrict__ W2, const float* __restrict__ b2)
{
    __shared__ uint32_t s_pT[16 * 132];   // [b][h2] half2
    __shared__ uint32_t s_ah[16 * 128];   // [v][h2] half2
    __shared__ uint32_t s_w2h[128];       // [h2] half2

    int t = threadIdx.x;
    int v0 = blockIdx.x * 16;

    for (int i = t; i < 16 * 128; i += 256) {
        int b = i & 15, h2 = i >> 4;
        __half2 h = __floats2half2_rn(g_pht[(2 * h2) * 16 + b], g_pht[(2 * h2 + 1) * 16 + b]);
        s_pT[b * 132 + h2] = *(uint32_t*)&h;
    }
    if (t < 128) {
        __half2 h = __floats2half2_rn(W2[2 * t], W2[2 * t + 1]);
        s_w2h[t] = *(uint32_t*)&h;
    }
    for (int i = t; i < 16 * 64; i += 256) {
        int r = i >> 6, c4 = i & 63;
        float4 v = *(const float4*)&g_ah[(size_t)(v0 + r) * H_ + c4 * 4];
        __half2 a = __floats2half2_rn(v.x, v.y);
        __half2 c = __floats2half2_rn(v.z, v.w);
        s_ah[r * 128 + c4 * 2]     = *(uint32_t*)&a;
        s_ah[r * 128 + c4 * 2 + 1] = *(uint32_t*)&c;
    }
    __syncthreads();

    int w = t >> 5, l = t & 31;
    int r = l >> 2, m = l & 3;
    float b2v = b2[0];

    #pragma unroll
    for (int vv = 0; vv < 2; vv++) {
        int vl = w * 2 + vv;
        float c[4] = {0.f, 0.f, 0.f, 0.f};
        #pragma unroll
        for (int s = 0; s < 16; s++) {
            int h2 = 8 * s + m;
            uint32_t av0 = s_ah[vl * 128 + h2];
            uint32_t av2 = s_ah[vl * 128 + h2 + 4];
            uint32_t p0 = s_pT[r * 132 + h2];
            uint32_t p1 = s_pT[(r + 8) * 132 + h2];
            uint32_t q0 = s_pT[r * 132 + h2 + 4];
            uint32_t q1 = s_pT[(r + 8) * 132 + h2 + 4];
            uint32_t a0, a1, a2, a3;
            asm("add.rn.f16x2 %0, %1, %2;" : "=r"(a0) : "r"(av0), "r"(p0));
            asm("add.rn.f16x2 %0, %1, %2;" : "=r"(a1) : "r"(av0), "r"(p1));
            asm("add.rn.f16x2 %0, %1, %2;" : "=r"(a2) : "r"(av2), "r"(q0));
            asm("add.rn.f16x2 %0, %1, %2;" : "=r"(a3) : "r"(av2), "r"(q1));
            asm("tanh.approx.f16x2 %0, %1;" : "=r"(a0) : "r"(a0));
            asm("tanh.approx.f16x2 %0, %1;" : "=r"(a1) : "r"(a1));
            asm("tanh.approx.f16x2 %0, %1;" : "=r"(a2) : "r"(a2));
            asm("tanh.approx.f16x2 %0, %1;" : "=r"(a3) : "r"(a3));
            uint32_t b0 = s_w2h[8 * s + m];
            uint32_t b1 = s_w2h[8 * s + m + 4];
            mma_f16(c, a0, a1, a2, a3, b0, b1);
        }
        if (m == 0) {
            int v = v0 + vl;
            g_scores[(size_t)r * V_ + v]       = c[0] + b2v;
            g_scores[(size_t)(r + 8) * V_ + v] = c[2] + b2v;
        }
    }
}

// ---------------- fused per-b LN over V: stats + normalize ----------------
__global__ __launch_bounds__(1024)
void k_rednorm(const float* __restrict__ g_pred,
               const float* __restrict__ b_pred,
               float* __restrict__ out)
{
    int b = blockIdx.x, t = threadIdx.x;
    const float4* row = (const float4*)&g_scores[(size_t)b * V_];
    float s1 = 0.f, s2 = 0.f;
    #pragma unroll
    for (int v = t; v < V_ / 4; v += 1024) {
        float4 x = row[v];
        s1 += x.x + x.y + x.z + x.w;
        s2 = fmaf(x.x, x.x, fmaf(x.y, x.y, fmaf(x.z, x.z, fmaf(x.w, x.w, s2))));
    }
    #pragma unroll
    for (int o = 16; o; o >>= 1) {
        s1 += __shfl_xor_sync(0xffffffffu, s1, o);
        s2 += __shfl_xor_sync(0xffffffffu, s2, o);
    }
    __shared__ float r1[32], r2[32], st[2];
    int w = t >> 5, ll = t & 31;
    if (ll == 0) { r1[w] = s1; r2[w] = s2; }
    __syncthreads();
    if (t < 32) {
        float a1 = r1[t], a2 = r2[t];
        #pragma unroll
        for (int o = 16; o; o >>= 1) {
            a1 += __shfl_xor_sync(0xffffffffu, a1, o);
            a2 += __shfl_xor_sync(0xffffffffu, a2, o);
        }
        if (t == 0) {
            float mean = a1 * (1.0f / V_);
            float var  = a2 * (1.0f / V_) - mean * mean;
            st[0] = mean;
            st[1] = rsqrtf(var + EPS_);
        }
    }
    __syncthreads();
    float mean = st[0], rstd = st[1];
    const float4* gp4 = (const float4*)g_pred;
    const float4* bp4 = (const float4*)b_pred;
    float4* out4 = (float4*)&out[(size_t)b * V_];
    #pragma unroll
    for (int v = t; v < V_ / 4; v += 1024) {
        float4 x = row[v];
        float4 g = gp4[v];
        float4 be = bp4[v];
        float4 o;
        o.x = (x.x - mean) * rstd * g.x + be.x;
        o.y = (x.y - mean) * rstd * g.y + be.y;
        o.z = (x.z - mean) * rstd * g.z + be.z;
        o.w = (x.w - mean) * rstd * g.w + be.w;
        out4[v] = o;
    }
}

// ---------------- launch ----------------
extern "C" void kernel_launch(void* const* d_in, const int* in_sizes, int n_in,
                              void* d_out, int out_size)
{
    const float* pe     = (const float*)d_in[0];
    const float* atc4   = (const float*)d_in[1];
    const float* Wp     = (const float*)d_in[2];
    const float* bp     = (const float*)d_in[3];
    const float* gp     = (const float*)d_in[4];
    const float* betap  = (const float*)d_in[5];
    const float* Wa     = (const float*)d_in[6];
    const float* ba     = (const float*)d_in[7];
    const float* ga     = (const float*)d_in[8];
    const float* betaa  = (const float*)d_in[9];
    const float* W1     = (const float*)d_in[10];
    const float* b1     = (const float*)d_in[11];
    const float* W2     = (const float*)d_in[12];
    const float* b2     = (const float*)d_in[13];
    const float* gpred  = (const float*)d_in[14];
    const float* bpred  = (const float*)d_in[15];
    float* out = (float*)d_out;
    (void)in_sizes; (void)n_in; (void)out_size;

    cudaFuncSetAttribute(k_fused, cudaFuncAttributeMaxDynamicSharedMemorySize, SMEM_SZ);

    k_prep<<<48, 256>>>(Wa, W1, pe, Wp, bp, gp, betap, b1);

    int tiles = (V_ + 63) / 64;   // 313
    k_fused<<<tiles, 256, SMEM_SZ>>>(atc4, ba, ga, betaa);

    k_score<<<V_ / 16, 256>>>(W2, b2);
    k_rednorm<<<B_, 1024>>>(gpred, bpred, out);
}

// round 9
// speedup vs baseline: 1.0153x; 1.0153x over previous
#include <cuda_runtime.h>
#include <cuda_bf16.h>
#include <cuda_fp16.h>
#include <cstdint>

#define B_   16
#define V_   20000
#define D_   256
#define H_   256
#define EPS_ 1e-5f

// ======================= helpers =======================
__device__ __forceinline__ uint32_t smem_u32(const void* p) {
    uint32_t a;
    asm("{ .reg .u64 t; cvta.to.shared.u64 t, %1; cvt.u32.u64 %0, t; }" : "=r"(a) : "l"(p));
    return a;
}
__device__ __forceinline__ void ldsm4(uint32_t* r, uint32_t addr) {
    asm volatile("ldmatrix.sync.aligned.m8n8.x4.shared.b16 {%0,%1,%2,%3}, [%4];"
        : "=r"(r[0]), "=r"(r[1]), "=r"(r[2]), "=r"(r[3]) : "r"(addr));
}
__device__ __forceinline__ void ldsm4t(uint32_t* r, uint32_t addr) {
    asm volatile("ldmatrix.sync.aligned.m8n8.x4.trans.shared.b16 {%0,%1,%2,%3}, [%4];"
        : "=r"(r[0]), "=r"(r[1]), "=r"(r[2]), "=r"(r[3]) : "r"(addr));
}
__device__ __forceinline__ void mma_bf16(float* c, const uint32_t* a, const uint32_t* b) {
    asm volatile("mma.sync.aligned.m16n8k16.row.col.f32.bf16.bf16.f32 "
        "{%0,%1,%2,%3}, {%4,%5,%6,%7}, {%8,%9}, {%0,%1,%2,%3};"
        : "+f"(c[0]), "+f"(c[1]), "+f"(c[2]), "+f"(c[3])
        : "r"(a[0]), "r"(a[1]), "r"(a[2]), "r"(a[3]), "r"(b[0]), "r"(b[1]));
}
__device__ __forceinline__ uint32_t pack2bf16(float a, float b) {
    unsigned short ua = __bfloat16_as_ushort(__float2bfloat16(a));
    unsigned short ub = __bfloat16_as_ushort(__float2bfloat16(b));
    return ((uint32_t)ub << 16) | ua;
}
__device__ __forceinline__ void cp16(uint32_t dst, const void* src) {
    asm volatile("cp.async.cg.shared.global [%0], [%1], 16;" :: "r"(dst), "l"(src));
}
#define CP_COMMIT() asm volatile("cp.async.commit_group;" ::: "memory")
#define CP_WAIT(n)  asm volatile("cp.async.wait_group %0;" :: "n"(n) : "memory")

// ======================= scratch =======================
__device__ float g_pht[H_ * B_];          // [h][b]
__device__ float g_ah[V_ * D_];
__device__ float g_scores[B_ * V_];
// split weights, NO transpose: [mat(2)][split(2)][k(256)][n(256)] bf16
__device__ __align__(16) __nv_bfloat16 g_Bs[2 * 2 * 256 * 256];

// ---------------- prep (blocks 0..31) + patient (blocks 32..47) ----------------
__global__ void k_prep(const float* __restrict__ Wa, const float* __restrict__ W1,
                       const float* __restrict__ pe, const float* __restrict__ Wp,
                       const float* __restrict__ bp, const float* __restrict__ gp,
                       const float* __restrict__ betap, const float* __restrict__ b1)
{
    if (blockIdx.x < 32) {
        int mat = blockIdx.x >> 4;
        int kg  = blockIdx.x & 15;
        int n   = threadIdx.x;
        const float* W = mat ? (W1 + (size_t)D_ * H_) : Wa;   // [k][n]
        __nv_bfloat16* dh = g_Bs + (size_t)(mat * 2 + 0) * 65536;
        __nv_bfloat16* dl = g_Bs + (size_t)(mat * 2 + 1) * 65536;
        #pragma unroll 4
        for (int kp = 0; kp < 16; kp++) {
            int k = kg * 16 + kp;
            float v = W[(size_t)k * 256 + n];
            __nv_bfloat16 h = __float2bfloat16(v);
            dh[(size_t)k * 256 + n] = h;
            dl[(size_t)k * 256 + n] = __float2bfloat16(v - __bfloat162float(h));
        }
        return;
    }
    int b = blockIdx.x - 32, d = threadIdx.x;
    __shared__ float s_pe[D_], s_p[D_];
    s_pe[d] = pe[b * D_ + d];
    __syncthreads();
    float acc = bp[d];
    #pragma unroll 8
    for (int k = 0; k < D_; k++) acc = fmaf(s_pe[k], Wp[k * D_ + d], acc);
    float s1 = acc, s2 = acc * acc;
    #pragma unroll
    for (int o = 16; o; o >>= 1) {
        s1 += __shfl_xor_sync(0xffffffffu, s1, o);
        s2 += __shfl_xor_sync(0xffffffffu, s2, o);
    }
    __shared__ float r1[8], r2[8], bc[2];
    int w = d >> 5, l = d & 31;
    if (l == 0) { r1[w] = s1; r2[w] = s2; }
    __syncthreads();
    if (d == 0) {
        float t1 = 0.f, t2 = 0.f;
        #pragma unroll
        for (int i = 0; i < 8; i++) { t1 += r1[i]; t2 += r2[i]; }
        float mean = t1 * (1.0f / D_);
        float var  = t2 * (1.0f / D_) - mean * mean;
        bc[0] = mean; bc[1] = rsqrtf(var + EPS_);
    }
    __syncthreads();
    s_p[d] = (acc - bc[0]) * bc[1] * gp[d] + betap[d];
    __syncthreads();
    float acc2 = b1[d];
    #pragma unroll 8
    for (int k = 0; k < D_; k++) acc2 = fmaf(s_p[k], W1[k * H_ + d], acc2);
    g_pht[d * B_ + b] = acc2;
}

// ---------------- fused HMMA kernel: 3-stage, 1 sync per chunk ----------------
static constexpr uint32_t A_HI   = 0;
static constexpr uint32_t A_LO   = 32768;
static constexpr uint32_t B_B0   = 65536;
static constexpr uint32_t B_STR  = 16640;     // per stage
static constexpr uint32_t SC_BA  = 98816;     // == B_B0 + 2*B_STR (slot 2)
static constexpr uint32_t SC_GA  = 99840;
static constexpr uint32_t SC_BE  = 100864;
static constexpr uint32_t SC_PS  = 101888;
static constexpr uint32_t SC_PQ  = 102912;
static constexpr uint32_t SC_MR  = 103936;
static constexpr uint32_t SMEM_SZ = 115456;   // 65536 + 3*16640

__global__ __launch_bounds__(256, 2)
void k_fused(const float* __restrict__ atc4,
             const float* __restrict__ ba,
             const float* __restrict__ ga,
             const float* __restrict__ betaa)
{
    extern __shared__ __align__(16) unsigned char smem[];
    uint32_t sb = smem_u32(smem);
    int tid = threadIdx.x;
    int wid = tid >> 5;
    int l   = tid & 31;
    int wm  = wid >> 2;
    int wn  = wid & 3;
    int quad = l >> 2;
    int tid4 = l & 3;
    int m0 = blockIdx.x * 64;

    auto issue = [&](int t) {
        int phase = t >> 4, c = t & 15;
        uint32_t bb = sb + B_B0 + (uint32_t)(t % 3) * B_STR;
        const __nv_bfloat16* bh = g_Bs + (size_t)(phase * 2) * 65536 + (size_t)c * 16 * 256;
        const __nv_bfloat16* bl = bh + 65536;
        #pragma unroll
        for (int it = 0; it < 2; it++) {
            int id = it * 256 + tid;       // 0..511
            int k = id >> 5, u = id & 31;
            uint32_t dst = bb + (uint32_t)k * 1040 + (uint32_t)u * 16;
            cp16(dst,       bh + (size_t)k * 256 + u * 8);
            cp16(dst + 512, bl + (size_t)k * 256 + u * 8);
        }
        CP_COMMIT();
    };

    issue(0);
    issue(1);

    // ---- convert atc4 tile -> bf16 hi/lo into swizzled A smem ----
    #pragma unroll
    for (int it = 0; it < 8; it++) {
        int id = it * 256 + tid;
        int row = id >> 5, u = id & 31;
        int gr = m0 + row;
        float f[8];
        if (gr < V_) {
            float4 v0 = *(const float4*)&atc4[(size_t)gr * 256 + u * 8];
            float4 v1 = *(const float4*)&atc4[(size_t)gr * 256 + u * 8 + 4];
            f[0]=v0.x; f[1]=v0.y; f[2]=v0.z; f[3]=v0.w;
            f[4]=v1.x; f[5]=v1.y; f[6]=v1.z; f[7]=v1.w;
        } else {
            #pragma unroll
            for (int i = 0; i < 8; i++) f[i] = 0.f;
        }
        float hf[8], lf[8];
        #pragma unroll
        for (int i = 0; i < 8; i++) {
            hf[i] = __bfloat162float(__float2bfloat16(f[i]));
            lf[i] = f[i] - hf[i];
        }
        uint4 hp, lp;
        hp.x = pack2bf16(hf[0], hf[1]); hp.y = pack2bf16(hf[2], hf[3]);
        hp.z = pack2bf16(hf[4], hf[5]); hp.w = pack2bf16(hf[6], hf[7]);
        lp.x = pack2bf16(lf[0], lf[1]); lp.y = pack2bf16(lf[2], lf[3]);
        lp.z = pack2bf16(lf[4], lf[5]); lp.w = pack2bf16(lf[6], lf[7]);
        uint32_t off = (uint32_t)row * 512 + (((uint32_t)u ^ ((uint32_t)row & 7)) << 4);
        *(uint4*)(smem + A_HI + off) = hp;
        *(uint4*)(smem + A_LO + off) = lp;
    }

    int ar = wm * 32 + (l & 15);
    uint32_t arx = (uint32_t)(ar & 7);
    uint32_t a_base = sb + A_HI + (uint32_t)ar * 512;
    uint32_t kusel = (uint32_t)((l >> 4) & 1);
    uint32_t b_lane = (uint32_t)(l & 15) * 1040 + (uint32_t)(wn * 64 + ((l >> 4) & 1) * 8) * 2;

    float acc[8][2][4];
    #pragma unroll
    for (int nb = 0; nb < 8; nb++)
        #pragma unroll
        for (int mb = 0; mb < 2; mb++)
            #pragma unroll
            for (int i = 0; i < 4; i++) acc[nb][mb][i] = 0.f;

    #pragma unroll 1
    for (int t = 0; t < 32; t++) {
        int c = t & 15;
        uint32_t bb = sb + B_B0 + (uint32_t)(t % 3) * B_STR;

        if (t == 31) { CP_WAIT(0); } else { CP_WAIT(1); }
        __syncthreads();            // data visible; slot (t+2)%3 fully consumed at t-1
        if (t < 30 && t != 15) issue(t + 2);
        if (t == 15) {
            ((float*)(smem + SC_BA))[tid] = ba[tid];
            ((float*)(smem + SC_GA))[tid] = ga[tid];
            ((float*)(smem + SC_BE))[tid] = betaa[tid];
        }

        uint32_t ku = (uint32_t)(c * 2) + kusel;
        uint32_t aa = a_base + ((ku ^ arx) << 4);
        uint32_t ah0[4], ah1[4], al0[4], al1[4];
        ldsm4(ah0, aa);
        ldsm4(ah1, aa + 8192);
        ldsm4(al0, aa + 32768);
        ldsm4(al1, aa + 40960);
        #pragma unroll
        for (int p = 0; p < 4; p++) {
            uint32_t bo = bb + b_lane + (uint32_t)(p * 32);
            uint32_t rh[4], rl[4];
            ldsm4t(rh, bo);
            ldsm4t(rl, bo + 512);
            #pragma unroll
            for (int q = 0; q < 2; q++) {
                int nb = p * 2 + q;
                mma_bf16(acc[nb][0], ah0, &rh[q * 2]);
                mma_bf16(acc[nb][0], ah0, &rl[q * 2]);
                mma_bf16(acc[nb][0], al0, &rh[q * 2]);
                mma_bf16(acc[nb][1], ah1, &rh[q * 2]);
                mma_bf16(acc[nb][1], ah1, &rl[q * 2]);
                mma_bf16(acc[nb][1], al1, &rh[q * 2]);
            }
        }

        if (t == 15) {
            __syncthreads();
            const float* s_ba = (const float*)(smem + SC_BA);
            const float* s_ga = (const float*)(smem + SC_GA);
            const float* s_be = (const float*)(smem + SC_BE);
            float* psum = (float*)(smem + SC_PS);
            float* psq  = (float*)(smem + SC_PQ);
            float* mrs  = (float*)(smem + SC_MR);

            #pragma unroll
            for (int mb = 0; mb < 2; mb++) {
                #pragma unroll
                for (int half = 0; half < 2; half++) {
                    float s1 = 0.f, s2 = 0.f;
                    #pragma unroll
                    for (int nb = 0; nb < 8; nb++) {
                        int col = wn * 64 + nb * 8 + tid4 * 2;
                        float x0 = acc[nb][mb][half * 2 + 0] + s_ba[col];
                        float x1 = acc[nb][mb][half * 2 + 1] + s_ba[col + 1];
                        s1 += x0 + x1;
                        s2 = fmaf(x0, x0, fmaf(x1, x1, s2));
                    }
                    s1 += __shfl_xor_sync(0xffffffffu, s1, 1);
                    s2 += __shfl_xor_sync(0xffffffffu, s2, 1);
                    s1 += __shfl_xor_sync(0xffffffffu, s1, 2);
                    s2 += __shfl_xor_sync(0xffffffffu, s2, 2);
                    if (tid4 == 0) {
                        int row = wm * 32 + mb * 16 + quad + half * 8;
                        psum[row * 4 + wn] = s1;
                        psq[row * 4 + wn]  = s2;
                    }
                }
            }
            __syncthreads();
            if (tid < 64) {
                float s1 = psum[tid * 4] + psum[tid * 4 + 1] + psum[tid * 4 + 2] + psum[tid * 4 + 3];
                float s2 = psq[tid * 4] + psq[tid * 4 + 1] + psq[tid * 4 + 2] + psq[tid * 4 + 3];
                float mean = s1 * (1.0f / 256.0f);
                float var  = s2 * (1.0f / 256.0f) - mean * mean;
                mrs[tid * 2]     = mean;
                mrs[tid * 2 + 1] = rsqrtf(var + EPS_);
            }
            __syncthreads();
            #pragma unroll
            for (int mb = 0; mb < 2; mb++) {
                #pragma unroll
                for (int half = 0; half < 2; half++) {
                    int row = wm * 32 + mb * 16 + quad + half * 8;
                    float mean = mrs[row * 2], rstd = mrs[row * 2 + 1];
                    #pragma unroll
                    for (int nb = 0; nb < 8; nb++) {
                        int col = wn * 64 + nb * 8 + tid4 * 2;
                        float x0 = acc[nb][mb][half * 2 + 0] + s_ba[col];
                        float x1 = acc[nb][mb][half * 2 + 1] + s_ba[col + 1];
                        float v0 = (x0 - mean) * rstd * s_ga[col] + s_be[col];
                        float v1 = (x1 - mean) * rstd * s_ga[col + 1] + s_be[col + 1];
                        float h0 = __bfloat162float(__float2bfloat16(v0));
                        float h1 = __bfloat162float(__float2bfloat16(v1));
                        uint32_t u = (uint32_t)(col >> 3);
                        uint32_t off = (uint32_t)row * 512 + ((u ^ ((uint32_t)row & 7)) << 4)
                                     + (uint32_t)tid4 * 4;
                        *(uint32_t*)(smem + A_HI + off) = pack2bf16(h0, h1);
                        *(uint32_t*)(smem + A_LO + off) = pack2bf16(v0 - h0, v1 - h1);
                    }
                }
            }
            #pragma unroll
            for (int nb = 0; nb < 8; nb++)
                #pragma unroll
                for (int mb = 0; mb < 2; mb++)
                    #pragma unroll
                    for (int i = 0; i < 4; i++) acc[nb][mb][i] = 0.f;
            __syncthreads();       // scratch dead + A rewritten before issue(17)/chunk 16
            issue(17);
        }

        if (t == 31) {
            #pragma unroll
            for (int mb = 0; mb < 2; mb++) {
                #pragma unroll
                for (int half = 0; half < 2; half++) {
                    int row = wm * 32 + mb * 16 + quad + half * 8;
                    int grow = m0 + row;
                    if (grow < V_) {
                        #pragma unroll
                        for (int nb = 0; nb < 8; nb++) {
                            int col = wn * 64 + nb * 8 + tid4 * 2;
                            float2 o = make_float2(acc[nb][mb][half * 2], acc[nb][mb][half * 2 + 1]);
                            *(float2*)&g_ah[(size_t)grow * 256 + col] = o;
                        }
                    }
                }
            }
        }
    }
}

// ---------------- score: f16x2 tanh (R7 version), 16 v per block ----------------
__global__ __launch_bounds__(256)
void k_score(const float* __restrict__ W2, const float* __restrict__ b2)
{
    __shared__ uint32_t s_pT[16 * 132];   // [b][h2] half2 pairs
    __shared__ uint32_t s_ah[16 * 128];   // [v][h2] half2 pairs
    __shared__ float4   s_w2[64];

    int t = threadIdx.x;
    int v0 = blockIdx.x * 16;

    for (int i = t; i < 16 * 128; i += 256) {
        int b = i & 15, h2 = i >> 4;
        float p0 = g_pht[(2 * h2) * 16 + b];
        float p1 = g_pht[(2 * h2 + 1) * 16 + b];
        __half2 h = __floats2half2_rn(p0, p1);
        s_pT[b * 132 + h2] = *(uint32_t*)&h;
    }
    if (t < 64) s_w2[t] = *(const float4*)&W2[t * 4];
    for (int i = t; i < 16 * 64; i += 256) {
        int r = i >> 6, c4 = i & 63;
        float4 v = *(const float4*)&g_ah[(size_t)(v0 + r) * H_ + c4 * 4];
        __half2 a = __floats2half2_rn(v.x, v.y);
        __half2 c = __floats2half2_rn(v.z, v.w);
        s_ah[r * 128 + c4 * 2]     = *(uint32_t*)&a;
        s_ah[r * 128 + c4 * 2 + 1] = *(uint32_t*)&c;
    }
    __syncthreads();

    int w = t >> 5, lane = t & 31;
    int b = lane & 15;
    int vloc = w * 2 + (lane >> 4);

    const uint4* arow = (const uint4*)&s_ah[vloc * 128];
    const uint4* prow = (const uint4*)&s_pT[b * 132];
    float acc = b2[0];
    #pragma unroll 8
    for (int u = 0; u < 32; u++) {
        uint4 a4 = arow[u];
        uint4 p4 = prow[u];
        float4 w0 = s_w2[u * 2];
        float4 w1 = s_w2[u * 2 + 1];
        uint32_t x0, x1, x2, x3;
        asm("add.rn.f16x2 %0, %1, %2;" : "=r"(x0) : "r"(a4.x), "r"(p4.x));
        asm("add.rn.f16x2 %0, %1, %2;" : "=r"(x1) : "r"(a4.y), "r"(p4.y));
        asm("add.rn.f16x2 %0, %1, %2;" : "=r"(x2) : "r"(a4.z), "r"(p4.z));
        asm("add.rn.f16x2 %0, %1, %2;" : "=r"(x3) : "r"(a4.w), "r"(p4.w));
        asm("tanh.approx.f16x2 %0, %1;" : "=r"(x0) : "r"(x0));
        asm("tanh.approx.f16x2 %0, %1;" : "=r"(x1) : "r"(x1));
        asm("tanh.approx.f16x2 %0, %1;" : "=r"(x2) : "r"(x2));
        asm("tanh.approx.f16x2 %0, %1;" : "=r"(x3) : "r"(x3));
        float2 f0 = __half22float2(*(__half2*)&x0);
        float2 f1 = __half22float2(*(__half2*)&x1);
        float2 f2 = __half22float2(*(__half2*)&x2);
        float2 f3 = __half22float2(*(__half2*)&x3);
        acc = fmaf(w0.x, f0.x, acc); acc = fmaf(w0.y, f0.y, acc);
        acc = fmaf(w0.z, f1.x, acc); acc = fmaf(w0.w, f1.y, acc);
        acc = fmaf(w1.x, f2.x, acc); acc = fmaf(w1.y, f2.y, acc);
        acc = fmaf(w1.z, f3.x, acc); acc = fmaf(w1.w, f3.y, acc);
    }
    g_scores[(size_t)b * V_ + v0 + vloc] = acc;
}

// ---------------- fused per-b LN over V: stats + normalize ----------------
__global__ __launch_bounds__(1024)
void k_rednorm(const float* __restrict__ g_pred,
               const float* __restrict__ b_pred,
               float* __restrict__ out)
{
    int b = blockIdx.x, t = threadIdx.x;
    const float4* row = (const float4*)&g_scores[(size_t)b * V_];
    float s1 = 0.f, s2 = 0.f;
    #pragma unroll
    for (int v = t; v < V_ / 4; v += 1024) {
        float4 x = row[v];
        s1 += x.x + x.y + x.z + x.w;
        s2 = fmaf(x.x, x.x, fmaf(x.y, x.y, fmaf(x.z, x.z, fmaf(x.w, x.w, s2))));
    }
    #pragma unroll
    for (int o = 16; o; o >>= 1) {
        s1 += __shfl_xor_sync(0xffffffffu, s1, o);
        s2 += __shfl_xor_sync(0xffffffffu, s2, o);
    }
    __shared__ float r1[32], r2[32], st[2];
    int w = t >> 5, ll = t & 31;
    if (ll == 0) { r1[w] = s1; r2[w] = s2; }
    __syncthreads();
    if (t < 32) {
        float a1 = r1[t], a2 = r2[t];
        #pragma unroll
        for (int o = 16; o; o >>= 1) {
            a1 += __shfl_xor_sync(0xffffffffu, a1, o);
            a2 += __shfl_xor_sync(0xffffffffu, a2, o);
        }
        if (t == 0) {
            float mean = a1 * (1.0f / V_);
            float var  = a2 * (1.0f / V_) - mean * mean;
            st[0] = mean;
            st[1] = rsqrtf(var + EPS_);
        }
    }
    __syncthreads();
    float mean = st[0], rstd = st[1];
    const float4* gp4 = (const float4*)g_pred;
    const float4* bp4 = (const float4*)b_pred;
    float4* out4 = (float4*)&out[(size_t)b * V_];
    #pragma unroll
    for (int v = t; v < V_ / 4; v += 1024) {
        float4 x = row[v];
        float4 g = gp4[v];
        float4 be = bp4[v];
        float4 o;
        o.x = (x.x - mean) * rstd * g.x + be.x;
        o.y = (x.y - mean) * rstd * g.y + be.y;
        o.z = (x.z - mean) * rstd * g.z + be.z;
        o.w = (x.w - mean) * rstd * g.w + be.w;
        out4[v] = o;
    }
}

// ---------------- launch ----------------
extern "C" void kernel_launch(void* const* d_in, const int* in_sizes, int n_in,
                              void* d_out, int out_size)
{
    const float* pe     = (const float*)d_in[0];
    const float* atc4   = (const float*)d_in[1];
    const float* Wp     = (const float*)d_in[2];
    const float* bp     = (const float*)d_in[3];
    const float* gp     = (const float*)d_in[4];
    const float* betap  = (const float*)d_in[5];
    const float* Wa     = (const float*)d_in[6];
    const float* ba     = (const float*)d_in[7];
    const float* ga     = (const float*)d_in[8];
    const float* betaa  = (const float*)d_in[9];
    const float* W1     = (const float*)d_in[10];
    const float* b1     = (const float*)d_in[11];
    const float* W2     = (const float*)d_in[12];
    const float* b2     = (const float*)d_in[13];
    const float* gpred  = (const float*)d_in[14];
    const float* bpred  = (const float*)d_in[15];
    float* out = (float*)d_out;
    (void)in_sizes; (void)n_in; (void)out_size;

    cudaFuncSetAttribute(k_fused, cudaFuncAttributeMaxDynamicSharedMemorySize, SMEM_SZ);

    k_prep<<<48, 256>>>(Wa, W1, pe, Wp, bp, gp, betap, b1);

    int tiles = (V_ + 63) / 64;   // 313
    k_fused<<<tiles, 256, SMEM_SZ>>>(atc4, ba, ga, betaa);

    k_score<<<V_ / 16, 256>>>(W2, b2);
    k_rednorm<<<B_, 1024>>>(gpred, bpred, out);
}

// round 10
// speedup vs baseline: 1.0343x; 1.0187x over previous
#include <cuda_runtime.h>
#include <cuda_bf16.h>
#include <cuda_fp16.h>
#include <cstdint>

#define B_   16
#define V_   20000
#define D_   256
#define H_   256
#define EPS_ 1e-5f

// ======================= helpers =======================
__device__ __forceinline__ uint32_t smem_u32(const void* p) {
    uint32_t a;
    asm("{ .reg .u64 t; cvta.to.shared.u64 t, %1; cvt.u32.u64 %0, t; }" : "=r"(a) : "l"(p));
    return a;
}
__device__ __forceinline__ void ldsm4(uint32_t* r, uint32_t addr) {
    asm volatile("ldmatrix.sync.aligned.m8n8.x4.shared.b16 {%0,%1,%2,%3}, [%4];"
        : "=r"(r[0]), "=r"(r[1]), "=r"(r[2]), "=r"(r[3]) : "r"(addr));
}
__device__ __forceinline__ void ldsm4t(uint32_t* r, uint32_t addr) {
    asm volatile("ldmatrix.sync.aligned.m8n8.x4.trans.shared.b16 {%0,%1,%2,%3}, [%4];"
        : "=r"(r[0]), "=r"(r[1]), "=r"(r[2]), "=r"(r[3]) : "r"(addr));
}
__device__ __forceinline__ void mma_bf16(float* c, const uint32_t* a, const uint32_t* b) {
    asm volatile("mma.sync.aligned.m16n8k16.row.col.f32.bf16.bf16.f32 "
        "{%0,%1,%2,%3}, {%4,%5,%6,%7}, {%8,%9}, {%0,%1,%2,%3};"
        : "+f"(c[0]), "+f"(c[1]), "+f"(c[2]), "+f"(c[3])
        : "r"(a[0]), "r"(a[1]), "r"(a[2]), "r"(a[3]), "r"(b[0]), "r"(b[1]));
}
__device__ __forceinline__ uint32_t pack2bf16(float a, float b) {
    unsigned short ua = __bfloat16_as_ushort(__float2bfloat16(a));
    unsigned short ub = __bfloat16_as_ushort(__float2bfloat16(b));
    return ((uint32_t)ub << 16) | ua;
}
__device__ __forceinline__ void cp16(uint32_t dst, const void* src) {
    asm volatile("cp.async.cg.shared.global [%0], [%1], 16;" :: "r"(dst), "l"(src));
}
#define CP_COMMIT() asm volatile("cp.async.commit_group;" ::: "memory")
#define CP_WAIT(n)  asm volatile("cp.async.wait_group %0;" :: "n"(n) : "memory")

// ======================= scratch =======================
__device__ float g_pht[H_ * B_];               // [h][b]
__device__ uint32_t g_ahh[V_ * (H_ / 2)];      // ah as half2 pairs [v][h2]
__device__ float g_scores[B_ * V_];            // [b][v]
// split weights, NO transpose: [mat(2)][split(2)][k(256)][n(256)] bf16
__device__ __align__(16) __nv_bfloat16 g_Bs[2 * 2 * 256 * 256];

// ---------------- prep (blocks 0..31) + patient (blocks 32..47) ----------------
__global__ void k_prep(const float* __restrict__ Wa, const float* __restrict__ W1,
                       const float* __restrict__ pe, const float* __restrict__ Wp,
                       const float* __restrict__ bp, const float* __restrict__ gp,
                       const float* __restrict__ betap, const float* __restrict__ b1)
{
    if (blockIdx.x < 32) {
        int mat = blockIdx.x >> 4;
        int kg  = blockIdx.x & 15;
        int n   = threadIdx.x;
        const float* W = mat ? (W1 + (size_t)D_ * H_) : Wa;   // [k][n]
        __nv_bfloat16* dh = g_Bs + (size_t)(mat * 2 + 0) * 65536;
        __nv_bfloat16* dl = g_Bs + (size_t)(mat * 2 + 1) * 65536;
        #pragma unroll 4
        for (int kp = 0; kp < 16; kp++) {
            int k = kg * 16 + kp;
            float v = W[(size_t)k * 256 + n];
            __nv_bfloat16 h = __float2bfloat16(v);
            dh[(size_t)k * 256 + n] = h;
            dl[(size_t)k * 256 + n] = __float2bfloat16(v - __bfloat162float(h));
        }
        return;
    }
    int b = blockIdx.x - 32, d = threadIdx.x;
    __shared__ float s_pe[D_], s_p[D_];
    s_pe[d] = pe[b * D_ + d];
    __syncthreads();
    float acc = bp[d];
    #pragma unroll 8
    for (int k = 0; k < D_; k++) acc = fmaf(s_pe[k], Wp[k * D_ + d], acc);
    float s1 = acc, s2 = acc * acc;
    #pragma unroll
    for (int o = 16; o; o >>= 1) {
        s1 += __shfl_xor_sync(0xffffffffu, s1, o);
        s2 += __shfl_xor_sync(0xffffffffu, s2, o);
    }
    __shared__ float r1[8], r2[8], bc[2];
    int w = d >> 5, l = d & 31;
    if (l == 0) { r1[w] = s1; r2[w] = s2; }
    __syncthreads();
    if (d == 0) {
        float t1 = 0.f, t2 = 0.f;
        #pragma unroll
        for (int i = 0; i < 8; i++) { t1 += r1[i]; t2 += r2[i]; }
        float mean = t1 * (1.0f / D_);
        float var  = t2 * (1.0f / D_) - mean * mean;
        bc[0] = mean; bc[1] = rsqrtf(var + EPS_);
    }
    __syncthreads();
    s_p[d] = (acc - bc[0]) * bc[1] * gp[d] + betap[d];
    __syncthreads();
    float acc2 = b1[d];
    #pragma unroll 8
    for (int k = 0; k < D_; k++) acc2 = fmaf(s_p[k], W1[k * H_ + d], acc2);
    g_pht[d * B_ + b] = acc2;
}

// ---------------- fused HMMA kernel (R7 2-stage structure) ----------------
static constexpr uint32_t A_HI  = 0;
static constexpr uint32_t A_LO  = 32768;
static constexpr uint32_t B_B0  = 65536;
static constexpr uint32_t B_STR = 16896;    // per stage
static constexpr uint32_t B_LOO = 8448;
static constexpr uint32_t P_BA  = 99328;
static constexpr uint32_t P_GA  = 100352;
static constexpr uint32_t P_BE  = 101376;
static constexpr uint32_t S_SUM = 102400;
static constexpr uint32_t S_SQ  = 103424;
static constexpr uint32_t S_MRS = 104448;
static constexpr uint32_t SMEM_SZ = 104960;

__global__ __launch_bounds__(256, 2)
void k_fused(const float* __restrict__ atc4,
             const float* __restrict__ ba,
             const float* __restrict__ ga,
             const float* __restrict__ betaa)
{
    extern __shared__ __align__(16) unsigned char smem[];
    uint32_t sb = smem_u32(smem);
    int tid = threadIdx.x;
    int wid = tid >> 5;
    int l   = tid & 31;
    int wm  = wid >> 2;
    int wn  = wid & 3;
    int quad = l >> 2;
    int tid4 = l & 3;
    int m0 = blockIdx.x * 64;

    auto issue = [&](int t) {
        int phase = t >> 4, c = t & 15;
        uint32_t bb = sb + B_B0 + (uint32_t)(t & 1) * B_STR;
        const __nv_bfloat16* bh = g_Bs + (size_t)(phase * 2) * 65536 + (size_t)c * 16 * 256;
        const __nv_bfloat16* bl = bh + 65536;
        #pragma unroll
        for (int it = 0; it < 2; it++) {
            int id = it * 256 + tid;       // 0..511
            int k = id >> 5, u = id & 31;
            uint32_t dst = (uint32_t)k * 528 + (uint32_t)u * 16;
            cp16(bb + dst,         bh + (size_t)k * 256 + u * 8);
            cp16(bb + B_LOO + dst, bl + (size_t)k * 256 + u * 8);
        }
        CP_COMMIT();
    };

    issue(0);
    issue(1);

    ((float*)(smem + P_BA))[tid] = ba[tid];
    ((float*)(smem + P_GA))[tid] = ga[tid];
    ((float*)(smem + P_BE))[tid] = betaa[tid];

    // ---- convert atc4 tile -> bf16 hi/lo into swizzled A smem ----
    #pragma unroll
    for (int it = 0; it < 8; it++) {
        int id = it * 256 + tid;
        int row = id >> 5, u = id & 31;
        int gr = m0 + row;
        float f[8];
        if (gr < V_) {
            float4 v0 = *(const float4*)&atc4[(size_t)gr * 256 + u * 8];
            float4 v1 = *(const float4*)&atc4[(size_t)gr * 256 + u * 8 + 4];
            f[0]=v0.x; f[1]=v0.y; f[2]=v0.z; f[3]=v0.w;
            f[4]=v1.x; f[5]=v1.y; f[6]=v1.z; f[7]=v1.w;
        } else {
            #pragma unroll
            for (int i = 0; i < 8; i++) f[i] = 0.f;
        }
        float hf[8], lf[8];
        #pragma unroll
        for (int i = 0; i < 8; i++) {
            hf[i] = __bfloat162float(__float2bfloat16(f[i]));
            lf[i] = f[i] - hf[i];
        }
        uint4 hp, lp;
        hp.x = pack2bf16(hf[0], hf[1]); hp.y = pack2bf16(hf[2], hf[3]);
        hp.z = pack2bf16(hf[4], hf[5]); hp.w = pack2bf16(hf[6], hf[7]);
        lp.x = pack2bf16(lf[0], lf[1]); lp.y = pack2bf16(lf[2], lf[3]);
        lp.z = pack2bf16(lf[4], lf[5]); lp.w = pack2bf16(lf[6], lf[7]);
        uint32_t off = (uint32_t)row * 512 + (((uint32_t)u ^ ((uint32_t)row & 7)) << 4);
        *(uint4*)(smem + A_HI + off) = hp;
        *(uint4*)(smem + A_LO + off) = lp;
    }

    int ar = wm * 32 + (l & 15);
    uint32_t arx = (uint32_t)(ar & 7);
    uint32_t a_base = sb + A_HI + (uint32_t)ar * 512;
    uint32_t kusel = (uint32_t)((l >> 4) & 1);
    uint32_t b_lane = (uint32_t)(l & 15) * 528 + (uint32_t)(wn * 64 + ((l >> 4) & 1) * 8) * 2;

    float acc[8][2][4];
    #pragma unroll
    for (int nb = 0; nb < 8; nb++)
        #pragma unroll
        for (int mb = 0; mb < 2; mb++)
            #pragma unroll
            for (int i = 0; i < 4; i++) acc[nb][mb][i] = 0.f;

    #pragma unroll 1
    for (int t = 0; t < 32; t++) {
        int c = t & 15;
        uint32_t bb = sb + B_B0 + (uint32_t)(t & 1) * B_STR;

        if (t == 31) { CP_WAIT(0); } else { CP_WAIT(1); }
        __syncthreads();

        uint32_t ku = (uint32_t)(c * 2) + kusel;
        uint32_t aa = a_base + ((ku ^ arx) << 4);
        uint32_t ah0[4], ah1[4], al0[4], al1[4];
        ldsm4(ah0, aa);
        ldsm4(ah1, aa + 8192);
        ldsm4(al0, aa + 32768);
        ldsm4(al1, aa + 40960);
        #pragma unroll
        for (int p = 0; p < 4; p++) {
            uint32_t bo = bb + b_lane + (uint32_t)(p * 32);
            uint32_t rh[4], rl[4];
            ldsm4t(rh, bo);
            ldsm4t(rl, bo + B_LOO);
            #pragma unroll
            for (int q = 0; q < 2; q++) {
                int nb = p * 2 + q;
                mma_bf16(acc[nb][0], ah0, &rh[q * 2]);
                mma_bf16(acc[nb][0], ah0, &rl[q * 2]);
                mma_bf16(acc[nb][0], al0, &rh[q * 2]);
                mma_bf16(acc[nb][1], ah1, &rh[q * 2]);
                mma_bf16(acc[nb][1], ah1, &rl[q * 2]);
                mma_bf16(acc[nb][1], al1, &rh[q * 2]);
            }
        }

        __syncthreads();
        if (t < 30) issue(t + 2);

        if (t == 15) {
            const float* s_ba = (const float*)(smem + P_BA);
            const float* s_ga = (const float*)(smem + P_GA);
            const float* s_be = (const float*)(smem + P_BE);
            float* psum = (float*)(smem + S_SUM);
            float* psq  = (float*)(smem + S_SQ);
            float* mrs  = (float*)(smem + S_MRS);

            #pragma unroll
            for (int mb = 0; mb < 2; mb++) {
                #pragma unroll
                for (int half = 0; half < 2; half++) {
                    float s1 = 0.f, s2 = 0.f;
                    #pragma unroll
                    for (int nb = 0; nb < 8; nb++) {
                        int col = wn * 64 + nb * 8 + tid4 * 2;
                        float x0 = acc[nb][mb][half * 2 + 0] + s_ba[col];
                        float x1 = acc[nb][mb][half * 2 + 1] + s_ba[col + 1];
                        s1 += x0 + x1;
                        s2 = fmaf(x0, x0, fmaf(x1, x1, s2));
                    }
                    s1 += __shfl_xor_sync(0xffffffffu, s1, 1);
                    s2 += __shfl_xor_sync(0xffffffffu, s2, 1);
                    s1 += __shfl_xor_sync(0xffffffffu, s1, 2);
                    s2 += __shfl_xor_sync(0xffffffffu, s2, 2);
                    if (tid4 == 0) {
                        int row = wm * 32 + mb * 16 + quad + half * 8;
                        psum[row * 4 + wn] = s1;
                        psq[row * 4 + wn]  = s2;
                    }
                }
            }
            __syncthreads();
            if (tid < 64) {
                float s1 = psum[tid * 4] + psum[tid * 4 + 1] + psum[tid * 4 + 2] + psum[tid * 4 + 3];
                float s2 = psq[tid * 4] + psq[tid * 4 + 1] + psq[tid * 4 + 2] + psq[tid * 4 + 3];
                float mean = s1 * (1.0f / 256.0f);
                float var  = s2 * (1.0f / 256.0f) - mean * mean;
                mrs[tid * 2]     = mean;
                mrs[tid * 2 + 1] = rsqrtf(var + EPS_);
            }
            __syncthreads();
            #pragma unroll
            for (int mb = 0; mb < 2; mb++) {
                #pragma unroll
                for (int half = 0; half < 2; half++) {
                    int row = wm * 32 + mb * 16 + quad + half * 8;
                    float mean = mrs[row * 2], rstd = mrs[row * 2 + 1];
                    #pragma unroll
                    for (int nb = 0; nb < 8; nb++) {
                        int col = wn * 64 + nb * 8 + tid4 * 2;
                        float x0 = acc[nb][mb][half * 2 + 0] + s_ba[col];
                        float x1 = acc[nb][mb][half * 2 + 1] + s_ba[col + 1];
                        float v0 = (x0 - mean) * rstd * s_ga[col] + s_be[col];
                        float v1 = (x1 - mean) * rstd * s_ga[col + 1] + s_be[col + 1];
                        float h0 = __bfloat162float(__float2bfloat16(v0));
                        float h1 = __bfloat162float(__float2bfloat16(v1));
                        uint32_t u = (uint32_t)(col >> 3);
                        uint32_t off = (uint32_t)row * 512 + ((u ^ ((uint32_t)row & 7)) << 4)
                                     + (uint32_t)tid4 * 4;
                        *(uint32_t*)(smem + A_HI + off) = pack2bf16(h0, h1);
                        *(uint32_t*)(smem + A_LO + off) = pack2bf16(v0 - h0, v1 - h1);
                    }
                }
            }
            #pragma unroll
            for (int nb = 0; nb < 8; nb++)
                #pragma unroll
                for (int mb = 0; mb < 2; mb++)
                    #pragma unroll
                    for (int i = 0; i < 4; i++) acc[nb][mb][i] = 0.f;
            __syncthreads();
        }

        if (t == 31) {
            // write ah as half2 (producer-side rounding == score-side rounding before)
            #pragma unroll
            for (int mb = 0; mb < 2; mb++) {
                #pragma unroll
                for (int half = 0; half < 2; half++) {
                    int row = wm * 32 + mb * 16 + quad + half * 8;
                    int grow = m0 + row;
                    if (grow < V_) {
                        #pragma unroll
                        for (int nb = 0; nb < 8; nb++) {
                            int col = wn * 64 + nb * 8 + tid4 * 2;
                            __half2 h = __floats2half2_rn(acc[nb][mb][half * 2],
                                                          acc[nb][mb][half * 2 + 1]);
                            g_ahh[(size_t)grow * 128 + (col >> 1)] = *(uint32_t*)&h;
                        }
                    }
                }
            }
        }
    }
}

// ---------------- score: f16x2 tanh, ah already half2 ----------------
__global__ __launch_bounds__(256)
void k_score(const float* __restrict__ W2, const float* __restrict__ b2)
{
    __shared__ uint32_t s_pT[16 * 132];   // [b][h2] half2 pairs
    __shared__ uint32_t s_ah[16 * 128];   // [v][h2] half2 pairs
    __shared__ float4   s_w2[64];

    int t = threadIdx.x;
    int v0 = blockIdx.x * 16;

    for (int i = t; i < 16 * 128; i += 256) {
        int b = i & 15, h2 = i >> 4;
        float p0 = g_pht[(2 * h2) * 16 + b];
        float p1 = g_pht[(2 * h2 + 1) * 16 + b];
        __half2 h = __floats2half2_rn(p0, p1);
        s_pT[b * 132 + h2] = *(uint32_t*)&h;
    }
    if (t < 64) s_w2[t] = *(const float4*)&W2[t * 4];
    // ah: straight uint4 copy (already half2)
    #pragma unroll
    for (int i = t; i < 16 * 32; i += 256) {
        int r = i >> 5, c = i & 31;
        ((uint4*)&s_ah[r * 128])[c] = ((const uint4*)&g_ahh[(size_t)(v0 + r) * 128])[c];
    }
    __syncthreads();

    int w = t >> 5, lane = t & 31;
    int b = lane & 15;
    int vloc = w * 2 + (lane >> 4);

    const uint4* arow = (const uint4*)&s_ah[vloc * 128];
    const uint4* prow = (const uint4*)&s_pT[b * 132];
    float acc = b2[0];
    #pragma unroll 8
    for (int u = 0; u < 32; u++) {
        uint4 a4 = arow[u];
        uint4 p4 = prow[u];
        float4 w0 = s_w2[u * 2];
        float4 w1 = s_w2[u * 2 + 1];
        uint32_t x0, x1, x2, x3;
        asm("add.rn.f16x2 %0, %1, %2;" : "=r"(x0) : "r"(a4.x), "r"(p4.x));
        asm("add.rn.f16x2 %0, %1, %2;" : "=r"(x1) : "r"(a4.y), "r"(p4.y));
        asm("add.rn.f16x2 %0, %1, %2;" : "=r"(x2) : "r"(a4.z), "r"(p4.z));
        asm("add.rn.f16x2 %0, %1, %2;" : "=r"(x3) : "r"(a4.w), "r"(p4.w));
        asm("tanh.approx.f16x2 %0, %1;" : "=r"(x0) : "r"(x0));
        asm("tanh.approx.f16x2 %0, %1;" : "=r"(x1) : "r"(x1));
        asm("tanh.approx.f16x2 %0, %1;" : "=r"(x2) : "r"(x2));
        asm("tanh.approx.f16x2 %0, %1;" : "=r"(x3) : "r"(x3));
        float2 f0 = __half22float2(*(__half2*)&x0);
        float2 f1 = __half22float2(*(__half2*)&x1);
        float2 f2 = __half22float2(*(__half2*)&x2);
        float2 f3 = __half22float2(*(__half2*)&x3);
        acc = fmaf(w0.x, f0.x, acc); acc = fmaf(w0.y, f0.y, acc);
        acc = fmaf(w0.z, f1.x, acc); acc = fmaf(w0.w, f1.y, acc);
        acc = fmaf(w1.x, f2.x, acc); acc = fmaf(w1.y, f2.y, acc);
        acc = fmaf(w1.z, f3.x, acc); acc = fmaf(w1.w, f3.y, acc);
    }
    g_scores[(size_t)b * V_ + v0 + vloc] = acc;
}

// ---------------- fused per-b LN over V: stats + normalize ----------------
__global__ __launch_bounds__(1024)
void k_rednorm(const float* __restrict__ g_pred,
               const float* __restrict__ b_pred,
               float* __restrict__ out)
{
    int b = blockIdx.x, t = threadIdx.x;
    const float4* row = (const float4*)&g_scores[(size_t)b * V_];
    float s1 = 0.f, s2 = 0.f;
    #pragma unroll
    for (int v = t; v < V_ / 4; v += 1024) {
        float4 x = row[v];
        s1 += x.x + x.y + x.z + x.w;
        s2 = fmaf(x.x, x.x, fmaf(x.y, x.y, fmaf(x.z, x.z, fmaf(x.w, x.w, s2))));
    }
    #pragma unroll
    for (int o = 16; o; o >>= 1) {
        s1 += __shfl_xor_sync(0xffffffffu, s1, o);
        s2 += __shfl_xor_sync(0xffffffffu, s2, o);
    }
    __shared__ float r1[32], r2[32], st[2];
    int w = t >> 5, ll = t & 31;
    if (ll == 0) { r1[w] = s1; r2[w] = s2; }
    __syncthreads();
    if (t < 32) {
        float a1 = r1[t], a2 = r2[t];
        #pragma unroll
        for (int o = 16; o; o >>= 1) {
            a1 += __shfl_xor_sync(0xffffffffu, a1, o);
            a2 += __shfl_xor_sync(0xffffffffu, a2, o);
        }
        if (t == 0) {
            float mean = a1 * (1.0f / V_);
            float var  = a2 * (1.0f / V_) - mean * mean;
            st[0] = mean;
            st[1] = rsqrtf(var + EPS_);
        }
    }
    __syncthreads();
    float mean = st[0], rstd = st[1];
    const float4* gp4 = (const float4*)g_pred;
    const float4* bp4 = (const float4*)b_pred;
    float4* out4 = (float4*)&out[(size_t)b * V_];
    #pragma unroll
    for (int v = t; v < V_ / 4; v += 1024) {
        float4 x = row[v];
        float4 g = gp4[v];
        float4 be = bp4[v];
        float4 o;
        o.x = (x.x - mean) * rstd * g.x + be.x;
        o.y = (x.y - mean) * rstd * g.y + be.y;
        o.z = (x.z - mean) * rstd * g.z + be.z;
        o.w = (x.w - mean) * rstd * g.w + be.w;
        out4[v] = o;
    }
}

// ---------------- launch ----------------
extern "C" void kernel_launch(void* const* d_in, const int* in_sizes, int n_in,
                              void* d_out, int out_size)
{
    const float* pe     = (const float*)d_in[0];
    const float* atc4   = (const float*)d_in[1];
    const float* Wp     = (const float*)d_in[2];
    const float* bp     = (const float*)d_in[3];
    const float* gp     = (const float*)d_in[4];
    const float* betap  = (const float*)d_in[5];
    const float* Wa     = (const float*)d_in[6];
    const float* ba     = (const float*)d_in[7];
    const float* ga     = (const float*)d_in[8];
    const float* betaa  = (const float*)d_in[9];
    const float* W1     = (const float*)d_in[10];
    const float* b1     = (const float*)d_in[11];
    const float* W2     = (const float*)d_in[12];
    const float* b2     = (const float*)d_in[13];
    const float* gpred  = (const float*)d_in[14];
    const float* bpred  = (const float*)d_in[15];
    float* out = (float*)d_out;
    (void)in_sizes; (void)n_in; (void)out_size;

    cudaFuncSetAttribute(k_fused, cudaFuncAttributeMaxDynamicSharedMemorySize, SMEM_SZ);

    k_prep<<<48, 256>>>(Wa, W1, pe, Wp, bp, gp, betap, b1);

    int tiles = (V_ + 63) / 64;   // 313
    k_fused<<<tiles, 256, SMEM_SZ>>>(atc4, ba, ga, betaa);

    k_score<<<V_ / 16, 256>>>(W2, b2);
    k_rednorm<<<B_, 1024>>>(gpred, bpred, out);
}

// round 11
// speedup vs baseline: 1.0375x; 1.0031x over previous
#include <cuda_runtime.h>
#include <cuda_bf16.h>
#include <cuda_fp16.h>
#include <cstdint>

#define B_   16
#define V_   20000
#define D_   256
#define H_   256
#define EPS_ 1e-5f

// ======================= helpers =======================
__device__ __forceinline__ uint32_t smem_u32(const void* p) {
    uint32_t a;
    asm("{ .reg .u64 t; cvta.to.shared.u64 t, %1; cvt.u32.u64 %0, t; }" : "=r"(a) : "l"(p));
    return a;
}
__device__ __forceinline__ void ldsm4(uint32_t* r, uint32_t addr) {
    asm volatile("ldmatrix.sync.aligned.m8n8.x4.shared.b16 {%0,%1,%2,%3}, [%4];"
        : "=r"(r[0]), "=r"(r[1]), "=r"(r[2]), "=r"(r[3]) : "r"(addr));
}
__device__ __forceinline__ void ldsm4t(uint32_t* r, uint32_t addr) {
    asm volatile("ldmatrix.sync.aligned.m8n8.x4.trans.shared.b16 {%0,%1,%2,%3}, [%4];"
        : "=r"(r[0]), "=r"(r[1]), "=r"(r[2]), "=r"(r[3]) : "r"(addr));
}
__device__ __forceinline__ void mma_bf16(float* c, const uint32_t* a, const uint32_t* b) {
    asm volatile("mma.sync.aligned.m16n8k16.row.col.f32.bf16.bf16.f32 "
        "{%0,%1,%2,%3}, {%4,%5,%6,%7}, {%8,%9}, {%0,%1,%2,%3};"
        : "+f"(c[0]), "+f"(c[1]), "+f"(c[2]), "+f"(c[3])
        : "r"(a[0]), "r"(a[1]), "r"(a[2]), "r"(a[3]), "r"(b[0]), "r"(b[1]));
}
__device__ __forceinline__ uint32_t pack2bf16(float a, float b) {
    unsigned short ua = __bfloat16_as_ushort(__float2bfloat16(a));
    unsigned short ub = __bfloat16_as_ushort(__float2bfloat16(b));
    return ((uint32_t)ub << 16) | ua;
}
__device__ __forceinline__ void cp16(uint32_t dst, const void* src) {
    asm volatile("cp.async.cg.shared.global [%0], [%1], 16;" :: "r"(dst), "l"(src));
}
#define CP_COMMIT() asm volatile("cp.async.commit_group;" ::: "memory")
#define CP_WAIT(n)  asm volatile("cp.async.wait_group %0;" :: "n"(n) : "memory")

// ======================= scratch =======================
__device__ float g_pht[H_ * B_];               // [h][b]
__device__ float g_scores[B_ * V_];            // [b][v]
// split weights, NO transpose: [mat(2)][split(2)][k(256)][n(256)] bf16
__device__ __align__(16) __nv_bfloat16 g_Bs[2 * 2 * 256 * 256];

// ---------------- prep (blocks 0..31) + patient (blocks 32..47) ----------------
__global__ void k_prep(const float* __restrict__ Wa, const float* __restrict__ W1,
                       const float* __restrict__ pe, const float* __restrict__ Wp,
                       const float* __restrict__ bp, const float* __restrict__ gp,
                       const float* __restrict__ betap, const float* __restrict__ b1)
{
    if (blockIdx.x < 32) {
        int mat = blockIdx.x >> 4;
        int kg  = blockIdx.x & 15;
        int n   = threadIdx.x;
        const float* W = mat ? (W1 + (size_t)D_ * H_) : Wa;   // [k][n]
        __nv_bfloat16* dh = g_Bs + (size_t)(mat * 2 + 0) * 65536;
        __nv_bfloat16* dl = g_Bs + (size_t)(mat * 2 + 1) * 65536;
        #pragma unroll 4
        for (int kp = 0; kp < 16; kp++) {
            int k = kg * 16 + kp;
            float v = W[(size_t)k * 256 + n];
            __nv_bfloat16 h = __float2bfloat16(v);
            dh[(size_t)k * 256 + n] = h;
            dl[(size_t)k * 256 + n] = __float2bfloat16(v - __bfloat162float(h));
        }
        return;
    }
    int b = blockIdx.x - 32, d = threadIdx.x;
    __shared__ float s_pe[D_], s_p[D_];
    s_pe[d] = pe[b * D_ + d];
    __syncthreads();
    float acc = bp[d];
    #pragma unroll 8
    for (int k = 0; k < D_; k++) acc = fmaf(s_pe[k], Wp[k * D_ + d], acc);
    float s1 = acc, s2 = acc * acc;
    #pragma unroll
    for (int o = 16; o; o >>= 1) {
        s1 += __shfl_xor_sync(0xffffffffu, s1, o);
        s2 += __shfl_xor_sync(0xffffffffu, s2, o);
    }
    __shared__ float r1[8], r2[8], bc[2];
    int w = d >> 5, l = d & 31;
    if (l == 0) { r1[w] = s1; r2[w] = s2; }
    __syncthreads();
    if (d == 0) {
        float t1 = 0.f, t2 = 0.f;
        #pragma unroll
        for (int i = 0; i < 8; i++) { t1 += r1[i]; t2 += r2[i]; }
        float mean = t1 * (1.0f / D_);
        float var  = t2 * (1.0f / D_) - mean * mean;
        bc[0] = mean; bc[1] = rsqrtf(var + EPS_);
    }
    __syncthreads();
    s_p[d] = (acc - bc[0]) * bc[1] * gp[d] + betap[d];
    __syncthreads();
    float acc2 = b1[d];
    #pragma unroll 8
    for (int k = 0; k < D_; k++) acc2 = fmaf(s_p[k], W1[k * H_ + d], acc2);
    g_pht[d * B_ + b] = acc2;
}

// ---------------- fused HMMA + LN + score kernel ----------------
static constexpr uint32_t A_HI  = 0;
static constexpr uint32_t A_LO  = 32768;
static constexpr uint32_t B_B0  = 65536;
static constexpr uint32_t B_STR = 16896;    // per stage
static constexpr uint32_t B_LOO = 8448;
static constexpr uint32_t P_BA  = 99328;
static constexpr uint32_t P_GA  = 100352;
static constexpr uint32_t P_BE  = 101376;
static constexpr uint32_t S_SUM = 102400;
static constexpr uint32_t S_SQ  = 103424;
static constexpr uint32_t S_MRS = 104448;
static constexpr uint32_t SMEM_SZ = 104960;
// score-epilogue overlays (A region dead after chunk 31):
static constexpr uint32_t S2_AH  = 0;         // 64 rows x 516B half2 (33024B)
static constexpr uint32_t S2_PHT = 34816;     // 256 h x 36B (9 uint32/h) = 9216B
static constexpr uint32_t S2_W2  = 44032;     // 256 floats

__global__ __launch_bounds__(256, 2)
void k_fused(const float* __restrict__ atc4,
             const float* __restrict__ ba,
             const float* __restrict__ ga,
             const float* __restrict__ betaa,
             const float* __restrict__ W2,
             const float* __restrict__ b2)
{
    extern __shared__ __align__(16) unsigned char smem[];
    uint32_t sb = smem_u32(smem);
    int tid = threadIdx.x;
    int wid = tid >> 5;
    int l   = tid & 31;
    int wm  = wid >> 2;
    int wn  = wid & 3;
    int quad = l >> 2;
    int tid4 = l & 3;
    int m0 = blockIdx.x * 64;

    auto issue = [&](int t) {
        int phase = t >> 4, c = t & 15;
        uint32_t bb = sb + B_B0 + (uint32_t)(t & 1) * B_STR;
        const __nv_bfloat16* bh = g_Bs + (size_t)(phase * 2) * 65536 + (size_t)c * 16 * 256;
        const __nv_bfloat16* bl = bh + 65536;
        #pragma unroll
        for (int it = 0; it < 2; it++) {
            int id = it * 256 + tid;
            int k = id >> 5, u = id & 31;
            uint32_t dst = (uint32_t)k * 528 + (uint32_t)u * 16;
            cp16(bb + dst,         bh + (size_t)k * 256 + u * 8);
            cp16(bb + B_LOO + dst, bl + (size_t)k * 256 + u * 8);
        }
        CP_COMMIT();
    };

    issue(0);
    issue(1);

    ((float*)(smem + P_BA))[tid] = ba[tid];
    ((float*)(smem + P_GA))[tid] = ga[tid];
    ((float*)(smem + P_BE))[tid] = betaa[tid];

    // ---- convert atc4 tile -> bf16 hi/lo into swizzled A smem ----
    #pragma unroll
    for (int it = 0; it < 8; it++) {
        int id = it * 256 + tid;
        int row = id >> 5, u = id & 31;
        int gr = m0 + row;
        float f[8];
        if (gr < V_) {
            float4 v0 = *(const float4*)&atc4[(size_t)gr * 256 + u * 8];
            float4 v1 = *(const float4*)&atc4[(size_t)gr * 256 + u * 8 + 4];
            f[0]=v0.x; f[1]=v0.y; f[2]=v0.z; f[3]=v0.w;
            f[4]=v1.x; f[5]=v1.y; f[6]=v1.z; f[7]=v1.w;
        } else {
            #pragma unroll
            for (int i = 0; i < 8; i++) f[i] = 0.f;
        }
        float hf[8], lf[8];
        #pragma unroll
        for (int i = 0; i < 8; i++) {
            hf[i] = __bfloat162float(__float2bfloat16(f[i]));
            lf[i] = f[i] - hf[i];
        }
        uint4 hp, lp;
        hp.x = pack2bf16(hf[0], hf[1]); hp.y = pack2bf16(hf[2], hf[3]);
        hp.z = pack2bf16(hf[4], hf[5]); hp.w = pack2bf16(hf[6], hf[7]);
        lp.x = pack2bf16(lf[0], lf[1]); lp.y = pack2bf16(lf[2], lf[3]);
        lp.z = pack2bf16(lf[4], lf[5]); lp.w = pack2bf16(lf[6], lf[7]);
        uint32_t off = (uint32_t)row * 512 + (((uint32_t)u ^ ((uint32_t)row & 7)) << 4);
        *(uint4*)(smem + A_HI + off) = hp;
        *(uint4*)(smem + A_LO + off) = lp;
    }

    int ar = wm * 32 + (l & 15);
    uint32_t arx = (uint32_t)(ar & 7);
    uint32_t a_base = sb + A_HI + (uint32_t)ar * 512;
    uint32_t kusel = (uint32_t)((l >> 4) & 1);
    uint32_t b_lane = (uint32_t)(l & 15) * 528 + (uint32_t)(wn * 64 + ((l >> 4) & 1) * 8) * 2;

    float acc[8][2][4];
    #pragma unroll
    for (int nb = 0; nb < 8; nb++)
        #pragma unroll
        for (int mb = 0; mb < 2; mb++)
            #pragma unroll
            for (int i = 0; i < 4; i++) acc[nb][mb][i] = 0.f;

    #pragma unroll 1
    for (int t = 0; t < 32; t++) {
        int c = t & 15;
        uint32_t bb = sb + B_B0 + (uint32_t)(t & 1) * B_STR;

        if (t == 31) { CP_WAIT(0); } else { CP_WAIT(1); }
        __syncthreads();

        uint32_t ku = (uint32_t)(c * 2) + kusel;
        uint32_t aa = a_base + ((ku ^ arx) << 4);
        uint32_t ah0[4], ah1[4], al0[4], al1[4];
        ldsm4(ah0, aa);
        ldsm4(ah1, aa + 8192);
        ldsm4(al0, aa + 32768);
        ldsm4(al1, aa + 40960);
        #pragma unroll
        for (int p = 0; p < 4; p++) {
            uint32_t bo = bb + b_lane + (uint32_t)(p * 32);
            uint32_t rh[4], rl[4];
            ldsm4t(rh, bo);
            ldsm4t(rl, bo + B_LOO);
            #pragma unroll
            for (int q = 0; q < 2; q++) {
                int nb = p * 2 + q;
                mma_bf16(acc[nb][0], ah0, &rh[q * 2]);
                mma_bf16(acc[nb][0], ah0, &rl[q * 2]);
                mma_bf16(acc[nb][0], al0, &rh[q * 2]);
                mma_bf16(acc[nb][1], ah1, &rh[q * 2]);
                mma_bf16(acc[nb][1], ah1, &rl[q * 2]);
                mma_bf16(acc[nb][1], al1, &rh[q * 2]);
            }
        }

        __syncthreads();
        if (t < 30) issue(t + 2);

        if (t == 15) {
            const float* s_ba = (const float*)(smem + P_BA);
            const float* s_ga = (const float*)(smem + P_GA);
            const float* s_be = (const float*)(smem + P_BE);
            float* psum = (float*)(smem + S_SUM);
            float* psq  = (float*)(smem + S_SQ);
            float* mrs  = (float*)(smem + S_MRS);

            #pragma unroll
            for (int mb = 0; mb < 2; mb++) {
                #pragma unroll
                for (int half = 0; half < 2; half++) {
                    float s1 = 0.f, s2 = 0.f;
                    #pragma unroll
                    for (int nb = 0; nb < 8; nb++) {
                        int col = wn * 64 + nb * 8 + tid4 * 2;
                        float x0 = acc[nb][mb][half * 2 + 0] + s_ba[col];
                        float x1 = acc[nb][mb][half * 2 + 1] + s_ba[col + 1];
                        s1 += x0 + x1;
                        s2 = fmaf(x0, x0, fmaf(x1, x1, s2));
                    }
                    s1 += __shfl_xor_sync(0xffffffffu, s1, 1);
                    s2 += __shfl_xor_sync(0xffffffffu, s2, 1);
                    s1 += __shfl_xor_sync(0xffffffffu, s1, 2);
                    s2 += __shfl_xor_sync(0xffffffffu, s2, 2);
                    if (tid4 == 0) {
                        int row = wm * 32 + mb * 16 + quad + half * 8;
                        psum[row * 4 + wn] = s1;
                        psq[row * 4 + wn]  = s2;
                    }
                }
            }
            __syncthreads();
            if (tid < 64) {
                float s1 = psum[tid * 4] + psum[tid * 4 + 1] + psum[tid * 4 + 2] + psum[tid * 4 + 3];
                float s2 = psq[tid * 4] + psq[tid * 4 + 1] + psq[tid * 4 + 2] + psq[tid * 4 + 3];
                float mean = s1 * (1.0f / 256.0f);
                float var  = s2 * (1.0f / 256.0f) - mean * mean;
                mrs[tid * 2]     = mean;
                mrs[tid * 2 + 1] = rsqrtf(var + EPS_);
            }
            __syncthreads();
            #pragma unroll
            for (int mb = 0; mb < 2; mb++) {
                #pragma unroll
                for (int half = 0; half < 2; half++) {
                    int row = wm * 32 + mb * 16 + quad + half * 8;
                    float mean = mrs[row * 2], rstd = mrs[row * 2 + 1];
                    #pragma unroll
                    for (int nb = 0; nb < 8; nb++) {
                        int col = wn * 64 + nb * 8 + tid4 * 2;
                        float x0 = acc[nb][mb][half * 2 + 0] + s_ba[col];
                        float x1 = acc[nb][mb][half * 2 + 1] + s_ba[col + 1];
                        float v0 = (x0 - mean) * rstd * s_ga[col] + s_be[col];
                        float v1 = (x1 - mean) * rstd * s_ga[col + 1] + s_be[col + 1];
                        float h0 = __bfloat162float(__float2bfloat16(v0));
                        float h1 = __bfloat162float(__float2bfloat16(v1));
                        uint32_t u = (uint32_t)(col >> 3);
                        uint32_t off = (uint32_t)row * 512 + ((u ^ ((uint32_t)row & 7)) << 4)
                                     + (uint32_t)tid4 * 4;
                        *(uint32_t*)(smem + A_HI + off) = pack2bf16(h0, h1);
                        *(uint32_t*)(smem + A_LO + off) = pack2bf16(v0 - h0, v1 - h1);
                    }
                }
            }
            #pragma unroll
            for (int nb = 0; nb < 8; nb++)
                #pragma unroll
                for (int mb = 0; mb < 2; mb++)
                    #pragma unroll
                    for (int i = 0; i < 4; i++) acc[nb][mb][i] = 0.f;
            __syncthreads();
        }
    }

    // ================= score epilogue (A region is dead) =================
    // 1) dump acc as half2 -> s_ah2[row][h2] (516B row stride)
    #pragma unroll
    for (int mb = 0; mb < 2; mb++) {
        #pragma unroll
        for (int half = 0; half < 2; half++) {
            int row = wm * 32 + mb * 16 + quad + half * 8;
            #pragma unroll
            for (int nb = 0; nb < 8; nb++) {
                int col = wn * 64 + nb * 8 + tid4 * 2;
                __half2 h = __floats2half2_rn(acc[nb][mb][half * 2],
                                              acc[nb][mb][half * 2 + 1]);
                *(uint32_t*)(smem + S2_AH + (uint32_t)row * 516 + (uint32_t)(col >> 1) * 4)
                    = *(uint32_t*)&h;
            }
        }
    }
    // 2) stage pht as half2 over b-pairs: s_pht2[h][b2], 36B/h; and W2 floats
    {
        #pragma unroll
        for (int e = tid; e < 2048; e += 256) {
            int h = e >> 3, b2 = e & 7;
            __half2 p = __floats2half2_rn(g_pht[h * 16 + 2 * b2], g_pht[h * 16 + 2 * b2 + 1]);
            *(uint32_t*)(smem + S2_PHT + (uint32_t)h * 36 + (uint32_t)b2 * 4) = *(uint32_t*)&p;
        }
        ((float*)(smem + S2_W2))[tid] = W2[tid];
    }
    __syncthreads();

    // 3) each thread: row r = tid>>2, batches 4*bq..4*bq+3
    {
        int r  = tid >> 2;
        int bq = tid & 3;
        const float* s_w2f = (const float*)(smem + S2_W2);
        float part0 = 0.f, part1 = 0.f, part2 = 0.f, part3 = 0.f;
        uint32_t ah_base  = sb + S2_AH + (uint32_t)r * 516;
        uint32_t pht_base = sb + S2_PHT + (uint32_t)bq * 8;

        #pragma unroll 4
        for (int h2 = 0; h2 < 128; h2++) {
            uint32_t a2;
            asm("ld.shared.b32 %0, [%1];" : "=r"(a2) : "r"(ah_base + h2 * 4));
            uint32_t blo, bhi;
            asm("prmt.b32 %0, %1, %1, 0x1010;" : "=r"(blo) : "r"(a2));
            asm("prmt.b32 %0, %1, %1, 0x3232;" : "=r"(bhi) : "r"(a2));
            uint32_t p00, p01, p10, p11;
            uint32_t pa = pht_base + (uint32_t)(2 * h2) * 36;
            asm("ld.shared.b32 %0, [%1];" : "=r"(p00) : "r"(pa));
            asm("ld.shared.b32 %0, [%1];" : "=r"(p01) : "r"(pa + 4));
            asm("ld.shared.b32 %0, [%1];" : "=r"(p10) : "r"(pa + 36));
            asm("ld.shared.b32 %0, [%1];" : "=r"(p11) : "r"(pa + 40));
            uint32_t x00, x01, x10, x11;
            asm("add.rn.f16x2 %0, %1, %2;" : "=r"(x00) : "r"(blo), "r"(p00));
            asm("add.rn.f16x2 %0, %1, %2;" : "=r"(x01) : "r"(blo), "r"(p01));
            asm("add.rn.f16x2 %0, %1, %2;" : "=r"(x10) : "r"(bhi), "r"(p10));
            asm("add.rn.f16x2 %0, %1, %2;" : "=r"(x11) : "r"(bhi), "r"(p11));
            asm("tanh.approx.f16x2 %0, %1;" : "=r"(x00) : "r"(x00));
            asm("tanh.approx.f16x2 %0, %1;" : "=r"(x01) : "r"(x01));
            asm("tanh.approx.f16x2 %0, %1;" : "=r"(x10) : "r"(x10));
            asm("tanh.approx.f16x2 %0, %1;" : "=r"(x11) : "r"(x11));
            float w0 = s_w2f[2 * h2];
            float w1 = s_w2f[2 * h2 + 1];
            float2 f00 = __half22float2(*(__half2*)&x00);
            float2 f01 = __half22float2(*(__half2*)&x01);
            float2 f10 = __half22float2(*(__half2*)&x10);
            float2 f11 = __half22float2(*(__half2*)&x11);
            part0 = fmaf(w0, f00.x, part0); part0 = fmaf(w1, f10.x, part0);
            part1 = fmaf(w0, f00.y, part1); part1 = fmaf(w1, f10.y, part1);
            part2 = fmaf(w0, f01.x, part2); part2 = fmaf(w1, f11.x, part2);
            part3 = fmaf(w0, f01.y, part3); part3 = fmaf(w1, f11.y, part3);
        }
        int grow = m0 + r;
        if (grow < V_) {
            float b2v = b2[0];
            g_scores[(size_t)(4 * bq + 0) * V_ + grow] = part0 + b2v;
            g_scores[(size_t)(4 * bq + 1) * V_ + grow] = part1 + b2v;
            g_scores[(size_t)(4 * bq + 2) * V_ + grow] = part2 + b2v;
            g_scores[(size_t)(4 * bq + 3) * V_ + grow] = part3 + b2v;
        }
    }
}

// ---------------- fused per-b LN over V: stats + normalize ----------------
__global__ __launch_bounds__(1024)
void k_rednorm(const float* __restrict__ g_pred,
               const float* __restrict__ b_pred,
               float* __restrict__ out)
{
    int b = blockIdx.x, t = threadIdx.x;
    const float4* row = (const float4*)&g_scores[(size_t)b * V_];
    float s1 = 0.f, s2 = 0.f;
    #pragma unroll
    for (int v = t; v < V_ / 4; v += 1024) {
        float4 x = row[v];
        s1 += x.x + x.y + x.z + x.w;
        s2 = fmaf(x.x, x.x, fmaf(x.y, x.y, fmaf(x.z, x.z, fmaf(x.w, x.w, s2))));
    }
    #pragma unroll
    for (int o = 16; o; o >>= 1) {
        s1 += __shfl_xor_sync(0xffffffffu, s1, o);
        s2 += __shfl_xor_sync(0xffffffffu, s2, o);
    }
    __shared__ float r1[32], r2[32], st[2];
    int w = t >> 5, ll = t & 31;
    if (ll == 0) { r1[w] = s1; r2[w] = s2; }
    __syncthreads();
    if (t < 32) {
        float a1 = r1[t], a2 = r2[t];
        #pragma unroll
        for (int o = 16; o; o >>= 1) {
            a1 += __shfl_xor_sync(0xffffffffu, a1, o);
            a2 += __shfl_xor_sync(0xffffffffu, a2, o);
        }
        if (t == 0) {
            float mean = a1 * (1.0f / V_);
            float var  = a2 * (1.0f / V_) - mean * mean;
            st[0] = mean;
            st[1] = rsqrtf(var + EPS_);
        }
    }
    __syncthreads();
    float mean = st[0], rstd = st[1];
    const float4* gp4 = (const float4*)g_pred;
    const float4* bp4 = (const float4*)b_pred;
    float4* out4 = (float4*)&out[(size_t)b * V_];
    #pragma unroll
    for (int v = t; v < V_ / 4; v += 1024) {
        float4 x = row[v];
        float4 g = gp4[v];
        float4 be = bp4[v];
        float4 o;
        o.x = (x.x - mean) * rstd * g.x + be.x;
        o.y = (x.y - mean) * rstd * g.y + be.y;
        o.z = (x.z - mean) * rstd * g.z + be.z;
        o.w = (x.w - mean) * rstd * g.w + be.w;
        out4[v] = o;
    }
}

// ---------------- launch ----------------
extern "C" void kernel_launch(void* const* d_in, const int* in_sizes, int n_in,
                              void* d_out, int out_size)
{
    const float* pe     = (const float*)d_in[0];
    const float* atc4   = (const float*)d_in[1];
    const float* Wp     = (const float*)d_in[2];
    const float* bp     = (const float*)d_in[3];
    const float* gp     = (const float*)d_in[4];
    const float* betap  = (const float*)d_in[5];
    const float* Wa     = (const float*)d_in[6];
    const float* ba     = (const float*)d_in[7];
    const float* ga     = (const float*)d_in[8];
    const float* betaa  = (const float*)d_in[9];
    const float* W1     = (const float*)d_in[10];
    const float* b1     = (const float*)d_in[11];
    const float* W2     = (const float*)d_in[12];
    const float* b2     = (const float*)d_in[13];
    const float* gpred  = (const float*)d_in[14];
    const float* bpred  = (const float*)d_in[15];
    float* out = (float*)d_out;
    (void)in_sizes; (void)n_in; (void)out_size;

    cudaFuncSetAttribute(k_fused, cudaFuncAttributeMaxDynamicSharedMemorySize, SMEM_SZ);

    k_prep<<<48, 256>>>(Wa, W1, pe, Wp, bp, gp, betap, b1);

    int tiles = (V_ + 63) / 64;   // 313
    k_fused<<<tiles, 256, SMEM_SZ>>>(atc4, ba, ga, betaa, W2, b2);

    k_rednorm<<<B_, 1024>>>(gpred, bpred, out);
}

// round 12
// speedup vs baseline: 1.1092x; 1.0691x over previous
#include <cuda_runtime.h>
#include <cuda_bf16.h>
#include <cuda_fp16.h>
#include <cstdint>

#define B_   16
#define V_   20000
#define D_   256
#define H_   256
#define EPS_ 1e-5f

// ======================= helpers =======================
__device__ __forceinline__ uint32_t smem_u32(const void* p) {
    uint32_t a;
    asm("{ .reg .u64 t; cvta.to.shared.u64 t, %1; cvt.u32.u64 %0, t; }" : "=r"(a) : "l"(p));
    return a;
}
__device__ __forceinline__ void ldsm4(uint32_t* r, uint32_t addr) {
    asm volatile("ldmatrix.sync.aligned.m8n8.x4.shared.b16 {%0,%1,%2,%3}, [%4];"
        : "=r"(r[0]), "=r"(r[1]), "=r"(r[2]), "=r"(r[3]) : "r"(addr));
}
__device__ __forceinline__ void ldsm4t(uint32_t* r, uint32_t addr) {
    asm volatile("ldmatrix.sync.aligned.m8n8.x4.trans.shared.b16 {%0,%1,%2,%3}, [%4];"
        : "=r"(r[0]), "=r"(r[1]), "=r"(r[2]), "=r"(r[3]) : "r"(addr));
}
__device__ __forceinline__ void mma_bf16(float* c, const uint32_t* a, const uint32_t* b) {
    asm volatile("mma.sync.aligned.m16n8k16.row.col.f32.bf16.bf16.f32 "
        "{%0,%1,%2,%3}, {%4,%5,%6,%7}, {%8,%9}, {%0,%1,%2,%3};"
        : "+f"(c[0]), "+f"(c[1]), "+f"(c[2]), "+f"(c[3])
        : "r"(a[0]), "r"(a[1]), "r"(a[2]), "r"(a[3]), "r"(b[0]), "r"(b[1]));
}
__device__ __forceinline__ uint32_t pack2bf16(float a, float b) {
    unsigned short ua = __bfloat16_as_ushort(__float2bfloat16(a));
    unsigned short ub = __bfloat16_as_ushort(__float2bfloat16(b));
    return ((uint32_t)ub << 16) | ua;
}
__device__ __forceinline__ void cp16(uint32_t dst, const void* src) {
    asm volatile("cp.async.cg.shared.global [%0], [%1], 16;" :: "r"(dst), "l"(src));
}
#define CP_COMMIT() asm volatile("cp.async.commit_group;" ::: "memory")
#define CP_WAIT(n)  asm volatile("cp.async.wait_group %0;" :: "n"(n) : "memory")

// ======================= scratch =======================
__device__ float g_pht[H_ * B_];               // [h][b]
__device__ float g_scores[B_ * V_];            // [b][v]
// split weights, NO transpose: [mat(2)][split(2)][k(256)][n(256)] bf16
__device__ __align__(16) __nv_bfloat16 g_Bs[2 * 2 * 256 * 256];

// ---------------- prep: blocks 0..127 weight split (1 elem/thread),
//                  blocks 128..143 patient (k-split x4) ----------------
__global__ __launch_bounds__(1024)
void k_prep(const float* __restrict__ Wa, const float* __restrict__ W1,
            const float* __restrict__ pe, const float* __restrict__ Wp,
            const float* __restrict__ bp, const float* __restrict__ gp,
            const float* __restrict__ betap, const float* __restrict__ b1)
{
    int tid = threadIdx.x;
    if (blockIdx.x < 128) {
        int e = blockIdx.x * 1024 + tid;          // 0..131071
        int mat = e >> 16;
        int rem = e & 65535;                      // k*256 + n
        const float* W = mat ? (W1 + (size_t)D_ * H_) : Wa;
        float v = W[rem];
        __nv_bfloat16 h = __float2bfloat16(v);
        g_Bs[(size_t)(mat * 2 + 0) * 65536 + rem] = h;
        g_Bs[(size_t)(mat * 2 + 1) * 65536 + rem] = __float2bfloat16(v - __bfloat162float(h));
        return;
    }
    // patient: block = batch b, 1024 threads: d = tid&255, q = tid>>8 (k-quarter)
    int b = blockIdx.x - 128;
    int d = tid & 255;
    int q = tid >> 8;
    __shared__ float s_pe[D_], s_p[D_];
    __shared__ float red[4][D_];
    __shared__ float r1[8], r2[8], bc[2];
    if (tid < 256) s_pe[tid] = pe[b * D_ + tid];
    __syncthreads();

    float part = 0.f;
    {
        const float* Wq = Wp + (size_t)(q * 64) * 256 + d;
        #pragma unroll 16
        for (int kk = 0; kk < 64; kk++)
            part = fmaf(s_pe[q * 64 + kk], Wq[(size_t)kk * 256], part);
    }
    red[q][d] = part;
    __syncthreads();

    float acc = 0.f;
    if (tid < 256) {
        acc = red[0][d] + red[1][d] + red[2][d] + red[3][d] + bp[d];
        float s1 = acc, s2 = acc * acc;
        #pragma unroll
        for (int o = 16; o; o >>= 1) {
            s1 += __shfl_xor_sync(0xffffffffu, s1, o);
            s2 += __shfl_xor_sync(0xffffffffu, s2, o);
        }
        if ((tid & 31) == 0) { r1[tid >> 5] = s1; r2[tid >> 5] = s2; }
    }
    __syncthreads();
    if (tid == 0) {
        float t1 = 0.f, t2 = 0.f;
        #pragma unroll
        for (int i = 0; i < 8; i++) { t1 += r1[i]; t2 += r2[i]; }
        float mean = t1 * (1.0f / D_);
        float var  = t2 * (1.0f / D_) - mean * mean;
        bc[0] = mean; bc[1] = rsqrtf(var + EPS_);
    }
    __syncthreads();
    if (tid < 256) s_p[d] = (acc - bc[0]) * bc[1] * gp[d] + betap[d];
    __syncthreads();

    float part2 = 0.f;
    {
        const float* W1q = W1 + (size_t)(q * 64) * 256 + d;
        #pragma unroll 16
        for (int kk = 0; kk < 64; kk++)
            part2 = fmaf(s_p[q * 64 + kk], W1q[(size_t)kk * 256], part2);
    }
    red[q][d] = part2;
    __syncthreads();
    if (tid < 256)
        g_pht[d * B_ + b] = red[0][d] + red[1][d] + red[2][d] + red[3][d] + b1[d];
}

// ---------------- fused HMMA + LN + score kernel (R11) ----------------
static constexpr uint32_t A_HI  = 0;
static constexpr uint32_t A_LO  = 32768;
static constexpr uint32_t B_B0  = 65536;
static constexpr uint32_t B_STR = 16896;    // per stage
static constexpr uint32_t B_LOO = 8448;
static constexpr uint32_t P_BA  = 99328;
static constexpr uint32_t P_GA  = 100352;
static constexpr uint32_t P_BE  = 101376;
static constexpr uint32_t S_SUM = 102400;
static constexpr uint32_t S_SQ  = 103424;
static constexpr uint32_t S_MRS = 104448;
static constexpr uint32_t SMEM_SZ = 104960;
// score-epilogue overlays (A region dead after chunk 31):
static constexpr uint32_t S2_AH  = 0;         // 64 rows x 516B half2
static constexpr uint32_t S2_PHT = 34816;     // 256 h x 36B
static constexpr uint32_t S2_W2  = 44032;     // 256 floats

__global__ __launch_bounds__(256, 2)
void k_fused(const float* __restrict__ atc4,
             const float* __restrict__ ba,
             const float* __restrict__ ga,
             const float* __restrict__ betaa,
             const float* __restrict__ W2,
             const float* __restrict__ b2)
{
    extern __shared__ __align__(16) unsigned char smem[];
    uint32_t sb = smem_u32(smem);
    int tid = threadIdx.x;
    int wid = tid >> 5;
    int l   = tid & 31;
    int wm  = wid >> 2;
    int wn  = wid & 3;
    int quad = l >> 2;
    int tid4 = l & 3;
    int m0 = blockIdx.x * 64;

    auto issue = [&](int t) {
        int phase = t >> 4, c = t & 15;
        uint32_t bb = sb + B_B0 + (uint32_t)(t & 1) * B_STR;
        const __nv_bfloat16* bh = g_Bs + (size_t)(phase * 2) * 65536 + (size_t)c * 16 * 256;
        const __nv_bfloat16* bl = bh + 65536;
        #pragma unroll
        for (int it = 0; it < 2; it++) {
            int id = it * 256 + tid;
            int k = id >> 5, u = id & 31;
            uint32_t dst = (uint32_t)k * 528 + (uint32_t)u * 16;
            cp16(bb + dst,         bh + (size_t)k * 256 + u * 8);
            cp16(bb + B_LOO + dst, bl + (size_t)k * 256 + u * 8);
        }
        CP_COMMIT();
    };

    issue(0);
    issue(1);

    ((float*)(smem + P_BA))[tid] = ba[tid];
    ((float*)(smem + P_GA))[tid] = ga[tid];
    ((float*)(smem + P_BE))[tid] = betaa[tid];

    // ---- convert atc4 tile -> bf16 hi/lo into swizzled A smem ----
    #pragma unroll
    for (int it = 0; it < 8; it++) {
        int id = it * 256 + tid;
        int row = id >> 5, u = id & 31;
        int gr = m0 + row;
        float f[8];
        if (gr < V_) {
            float4 v0 = *(const float4*)&atc4[(size_t)gr * 256 + u * 8];
            float4 v1 = *(const float4*)&atc4[(size_t)gr * 256 + u * 8 + 4];
            f[0]=v0.x; f[1]=v0.y; f[2]=v0.z; f[3]=v0.w;
            f[4]=v1.x; f[5]=v1.y; f[6]=v1.z; f[7]=v1.w;
        } else {
            #pragma unroll
            for (int i = 0; i < 8; i++) f[i] = 0.f;
        }
        float hf[8], lf[8];
        #pragma unroll
        for (int i = 0; i < 8; i++) {
            hf[i] = __bfloat162float(__float2bfloat16(f[i]));
            lf[i] = f[i] - hf[i];
        }
        uint4 hp, lp;
        hp.x = pack2bf16(hf[0], hf[1]); hp.y = pack2bf16(hf[2], hf[3]);
        hp.z = pack2bf16(hf[4], hf[5]); hp.w = pack2bf16(hf[6], hf[7]);
        lp.x = pack2bf16(lf[0], lf[1]); lp.y = pack2bf16(lf[2], lf[3]);
        lp.z = pack2bf16(lf[4], lf[5]); lp.w = pack2bf16(lf[6], lf[7]);
        uint32_t off = (uint32_t)row * 512 + (((uint32_t)u ^ ((uint32_t)row & 7)) << 4);
        *(uint4*)(smem + A_HI + off) = hp;
        *(uint4*)(smem + A_LO + off) = lp;
    }

    int ar = wm * 32 + (l & 15);
    uint32_t arx = (uint32_t)(ar & 7);
    uint32_t a_base = sb + A_HI + (uint32_t)ar * 512;
    uint32_t kusel = (uint32_t)((l >> 4) & 1);
    uint32_t b_lane = (uint32_t)(l & 15) * 528 + (uint32_t)(wn * 64 + ((l >> 4) & 1) * 8) * 2;

    float acc[8][2][4];
    #pragma unroll
    for (int nb = 0; nb < 8; nb++)
        #pragma unroll
        for (int mb = 0; mb < 2; mb++)
            #pragma unroll
            for (int i = 0; i < 4; i++) acc[nb][mb][i] = 0.f;

    #pragma unroll 1
    for (int t = 0; t < 32; t++) {
        int c = t & 15;
        uint32_t bb = sb + B_B0 + (uint32_t)(t & 1) * B_STR;

        if (t == 31) { CP_WAIT(0); } else { CP_WAIT(1); }
        __syncthreads();

        uint32_t ku = (uint32_t)(c * 2) + kusel;
        uint32_t aa = a_base + ((ku ^ arx) << 4);
        uint32_t ah0[4], ah1[4], al0[4], al1[4];
        ldsm4(ah0, aa);
        ldsm4(ah1, aa + 8192);
        ldsm4(al0, aa + 32768);
        ldsm4(al1, aa + 40960);
        #pragma unroll
        for (int p = 0; p < 4; p++) {
            uint32_t bo = bb + b_lane + (uint32_t)(p * 32);
            uint32_t rh[4], rl[4];
            ldsm4t(rh, bo);
            ldsm4t(rl, bo + B_LOO);
            #pragma unroll
            for (int q = 0; q < 2; q++) {
                int nb = p * 2 + q;
                mma_bf16(acc[nb][0], ah0, &rh[q * 2]);
                mma_bf16(acc[nb][0], ah0, &rl[q * 2]);
                mma_bf16(acc[nb][0], al0, &rh[q * 2]);
                mma_bf16(acc[nb][1], ah1, &rh[q * 2]);
                mma_bf16(acc[nb][1], ah1, &rl[q * 2]);
                mma_bf16(acc[nb][1], al1, &rh[q * 2]);
            }
        }

        __syncthreads();
        if (t < 30) issue(t + 2);

        if (t == 15) {
            const float* s_ba = (const float*)(smem + P_BA);
            const float* s_ga = (const float*)(smem + P_GA);
            const float* s_be = (const float*)(smem + P_BE);
            float* psum = (float*)(smem + S_SUM);
            float* psq  = (float*)(smem + S_SQ);
            float* mrs  = (float*)(smem + S_MRS);

            #pragma unroll
            for (int mb = 0; mb < 2; mb++) {
                #pragma unroll
                for (int half = 0; half < 2; half++) {
                    float s1 = 0.f, s2 = 0.f;
                    #pragma unroll
                    for (int nb = 0; nb < 8; nb++) {
                        int col = wn * 64 + nb * 8 + tid4 * 2;
                        float x0 = acc[nb][mb][half * 2 + 0] + s_ba[col];
                        float x1 = acc[nb][mb][half * 2 + 1] + s_ba[col + 1];
                        s1 += x0 + x1;
                        s2 = fmaf(x0, x0, fmaf(x1, x1, s2));
                    }
                    s1 += __shfl_xor_sync(0xffffffffu, s1, 1);
                    s2 += __shfl_xor_sync(0xffffffffu, s2, 1);
                    s1 += __shfl_xor_sync(0xffffffffu, s1, 2);
                    s2 += __shfl_xor_sync(0xffffffffu, s2, 2);
                    if (tid4 == 0) {
                        int row = wm * 32 + mb * 16 + quad + half * 8;
                        psum[row * 4 + wn] = s1;
                        psq[row * 4 + wn]  = s2;
                    }
                }
            }
            __syncthreads();
            if (tid < 64) {
                float s1 = psum[tid * 4] + psum[tid * 4 + 1] + psum[tid * 4 + 2] + psum[tid * 4 + 3];
                float s2 = psq[tid * 4] + psq[tid * 4 + 1] + psq[tid * 4 + 2] + psq[tid * 4 + 3];
                float mean = s1 * (1.0f / 256.0f);
                float var  = s2 * (1.0f / 256.0f) - mean * mean;
                mrs[tid * 2]     = mean;
                mrs[tid * 2 + 1] = rsqrtf(var + EPS_);
            }
            __syncthreads();
            #pragma unroll
            for (int mb = 0; mb < 2; mb++) {
                #pragma unroll
                for (int half = 0; half < 2; half++) {
                    int row = wm * 32 + mb * 16 + quad + half * 8;
                    float mean = mrs[row * 2], rstd = mrs[row * 2 + 1];
                    #pragma unroll
                    for (int nb = 0; nb < 8; nb++) {
                        int col = wn * 64 + nb * 8 + tid4 * 2;
                        float x0 = acc[nb][mb][half * 2 + 0] + s_ba[col];
                        float x1 = acc[nb][mb][half * 2 + 1] + s_ba[col + 1];
                        float v0 = (x0 - mean) * rstd * s_ga[col] + s_be[col];
                        float v1 = (x1 - mean) * rstd * s_ga[col + 1] + s_be[col + 1];
                        float h0 = __bfloat162float(__float2bfloat16(v0));
                        float h1 = __bfloat162float(__float2bfloat16(v1));
                        uint32_t u = (uint32_t)(col >> 3);
                        uint32_t off = (uint32_t)row * 512 + ((u ^ ((uint32_t)row & 7)) << 4)
                                     + (uint32_t)tid4 * 4;
                        *(uint32_t*)(smem + A_HI + off) = pack2bf16(h0, h1);
                        *(uint32_t*)(smem + A_LO + off) = pack2bf16(v0 - h0, v1 - h1);
                    }
                }
            }
            #pragma unroll
            for (int nb = 0; nb < 8; nb++)
                #pragma unroll
                for (int mb = 0; mb < 2; mb++)
                    #pragma unroll
                    for (int i = 0; i < 4; i++) acc[nb][mb][i] = 0.f;
            __syncthreads();
        }
    }

    // ================= score epilogue (A region is dead) =================
    #pragma unroll
    for (int mb = 0; mb < 2; mb++) {
        #pragma unroll
        for (int half = 0; half < 2; half++) {
            int row = wm * 32 + mb * 16 + quad + half * 8;
            #pragma unroll
            for (int nb = 0; nb < 8; nb++) {
                int col = wn * 64 + nb * 8 + tid4 * 2;
                __half2 h = __floats2half2_rn(acc[nb][mb][half * 2],
                                              acc[nb][mb][half * 2 + 1]);
                *(uint32_t*)(smem + S2_AH + (uint32_t)row * 516 + (uint32_t)(col >> 1) * 4)
                    = *(uint32_t*)&h;
            }
        }
    }
    {
        #pragma unroll
        for (int e = tid; e < 2048; e += 256) {
            int h = e >> 3, b2i = e & 7;
            __half2 p = __floats2half2_rn(g_pht[h * 16 + 2 * b2i], g_pht[h * 16 + 2 * b2i + 1]);
            *(uint32_t*)(smem + S2_PHT + (uint32_t)h * 36 + (uint32_t)b2i * 4) = *(uint32_t*)&p;
        }
        ((float*)(smem + S2_W2))[tid] = W2[tid];
    }
    __syncthreads();

    {
        int r  = tid >> 2;
        int bq = tid & 3;
        const float* s_w2f = (const float*)(smem + S2_W2);
        float part0 = 0.f, part1 = 0.f, part2 = 0.f, part3 = 0.f;
        uint32_t ah_base  = sb + S2_AH + (uint32_t)r * 516;
        uint32_t pht_base = sb + S2_PHT + (uint32_t)bq * 8;

        #pragma unroll 4
        for (int h2 = 0; h2 < 128; h2++) {
            uint32_t a2;
            asm("ld.shared.b32 %0, [%1];" : "=r"(a2) : "r"(ah_base + h2 * 4));
            uint32_t blo, bhi;
            asm("prmt.b32 %0, %1, %1, 0x1010;" : "=r"(blo) : "r"(a2));
            asm("prmt.b32 %0, %1, %1, 0x3232;" : "=r"(bhi) : "r"(a2));
            uint32_t p00, p01, p10, p11;
            uint32_t pa = pht_base + (uint32_t)(2 * h2) * 36;
            asm("ld.shared.b32 %0, [%1];" : "=r"(p00) : "r"(pa));
            asm("ld.shared.b32 %0, [%1];" : "=r"(p01) : "r"(pa + 4));
            asm("ld.shared.b32 %0, [%1];" : "=r"(p10) : "r"(pa + 36));
            asm("ld.shared.b32 %0, [%1];" : "=r"(p11) : "r"(pa + 40));
            uint32_t x00, x01, x10, x11;
            asm("add.rn.f16x2 %0, %1, %2;" : "=r"(x00) : "r"(blo), "r"(p00));
            asm("add.rn.f16x2 %0, %1, %2;" : "=r"(x01) : "r"(blo), "r"(p01));
            asm("add.rn.f16x2 %0, %1, %2;" : "=r"(x10) : "r"(bhi), "r"(p10));
            asm("add.rn.f16x2 %0, %1, %2;" : "=r"(x11) : "r"(bhi), "r"(p11));
            asm("tanh.approx.f16x2 %0, %1;" : "=r"(x00) : "r"(x00));
            asm("tanh.approx.f16x2 %0, %1;" : "=r"(x01) : "r"(x01));
            asm("tanh.approx.f16x2 %0, %1;" : "=r"(x10) : "r"(x10));
            asm("tanh.approx.f16x2 %0, %1;" : "=r"(x11) : "r"(x11));
            float w0 = s_w2f[2 * h2];
            float w1 = s_w2f[2 * h2 + 1];
            float2 f00 = __half22float2(*(__half2*)&x00);
            float2 f01 = __half22float2(*(__half2*)&x01);
            float2 f10 = __half22float2(*(__half2*)&x10);
            float2 f11 = __half22float2(*(__half2*)&x11);
            part0 = fmaf(w0, f00.x, part0); part0 = fmaf(w1, f10.x, part0);
            part1 = fmaf(w0, f00.y, part1); part1 = fmaf(w1, f10.y, part1);
            part2 = fmaf(w0, f01.x, part2); part2 = fmaf(w1, f11.x, part2);
            part3 = fmaf(w0, f01.y, part3); part3 = fmaf(w1, f11.y, part3);
        }
        int grow = m0 + r;
        if (grow < V_) {
            float b2v = b2[0];
            g_scores[(size_t)(4 * bq + 0) * V_ + grow] = part0 + b2v;
            g_scores[(size_t)(4 * bq + 1) * V_ + grow] = part1 + b2v;
            g_scores[(size_t)(4 * bq + 2) * V_ + grow] = part2 + b2v;
            g_scores[(size_t)(4 * bq + 3) * V_ + grow] = part3 + b2v;
        }
    }
}

// ---------------- fused per-b LN over V: stats + normalize ----------------
__global__ __launch_bounds__(1024)
void k_rednorm(const float* __restrict__ g_pred,
               const float* __restrict__ b_pred,
               float* __restrict__ out)
{
    int b = blockIdx.x, t = threadIdx.x;
    const float4* row = (const float4*)&g_scores[(size_t)b * V_];
    float s1 = 0.f, s2 = 0.f;
    #pragma unroll
    for (int v = t; v < V_ / 4; v += 1024) {
        float4 x = row[v];
        s1 += x.x + x.y + x.z + x.w;
        s2 = fmaf(x.x, x.x, fmaf(x.y, x.y, fmaf(x.z, x.z, fmaf(x.w, x.w, s2))));
    }
    #pragma unroll
    for (int o = 16; o; o >>= 1) {
        s1 += __shfl_xor_sync(0xffffffffu, s1, o);
        s2 += __shfl_xor_sync(0xffffffffu, s2, o);
    }
    __shared__ float r1[32], r2[32], st[2];
    int w = t >> 5, ll = t & 31;
    if (ll == 0) { r1[w] = s1; r2[w] = s2; }
    __syncthreads();
    if (t < 32) {
        float a1 = r1[t], a2 = r2[t];
        #pragma unroll
        for (int o = 16; o; o >>= 1) {
            a1 += __shfl_xor_sync(0xffffffffu, a1, o);
            a2 += __shfl_xor_sync(0xffffffffu, a2, o);
        }
        if (t == 0) {
            float mean = a1 * (1.0f / V_);
            float var  = a2 * (1.0f / V_) - mean * mean;
            st[0] = mean;
            st[1] = rsqrtf(var + EPS_);
        }
    }
    __syncthreads();
    float mean = st[0], rstd = st[1];
    const float4* gp4 = (const float4*)g_pred;
    const float4* bp4 = (const float4*)b_pred;
    float4* out4 = (float4*)&out[(size_t)b * V_];
    #pragma unroll
    for (int v = t; v < V_ / 4; v += 1024) {
        float4 x = row[v];
        float4 g = gp4[v];
        float4 be = bp4[v];
        float4 o;
        o.x = (x.x - mean) * rstd * g.x + be.x;
        o.y = (x.y - mean) * rstd * g.y + be.y;
        o.z = (x.z - mean) * rstd * g.z + be.z;
        o.w = (x.w - mean) * rstd * g.w + be.w;
        out4[v] = o;
    }
}

// ---------------- launch ----------------
extern "C" void kernel_launch(void* const* d_in, const int* in_sizes, int n_in,
                              void* d_out, int out_size)
{
    const float* pe     = (const float*)d_in[0];
    const float* atc4   = (const float*)d_in[1];
    const float* Wp     = (const float*)d_in[2];
    const float* bp     = (const float*)d_in[3];
    const float* gp     = (const float*)d_in[4];
    const float* betap  = (const float*)d_in[5];
    const float* Wa     = (const float*)d_in[6];
    const float* ba     = (const float*)d_in[7];
    const float* ga     = (const float*)d_in[8];
    const float* betaa  = (const float*)d_in[9];
    const float* W1     = (const float*)d_in[10];
    const float* b1     = (const float*)d_in[11];
    const float* W2     = (const float*)d_in[12];
    const float* b2     = (const float*)d_in[13];
    const float* gpred  = (const float*)d_in[14];
    const float* bpred  = (const float*)d_in[15];
    float* out = (float*)d_out;
    (void)in_sizes; (void)n_in; (void)out_size;

    cudaFuncSetAttribute(k_fused, cudaFuncAttributeMaxDynamicSharedMemorySize, SMEM_SZ);

    k_prep<<<144, 1024>>>(Wa, W1, pe, Wp, bp, gp, betap, b1);

    int tiles = (V_ + 63) / 64;   // 313
    k_fused<<<tiles, 256, SMEM_SZ>>>(atc4, ba, ga, betaa, W2, b2);

    k_rednorm<<<B_, 1024>>>(gpred, bpred, out);
}

// round 13
// speedup vs baseline: 1.1984x; 1.0805x over previous
#include <cuda_runtime.h>
#include <cuda_bf16.h>
#include <cuda_fp16.h>
#include <cstdint>

#define B_   16
#define V_   20000
#define D_   256
#define H_   256
#define EPS_ 1e-5f

// ======================= helpers =======================
__device__ __forceinline__ uint32_t smem_u32(const void* p) {
    uint32_t a;
    asm("{ .reg .u64 t; cvta.to.shared.u64 t, %1; cvt.u32.u64 %0, t; }" : "=r"(a) : "l"(p));
    return a;
}
__device__ __forceinline__ void ldsm4(uint32_t* r, uint32_t addr) {
    asm volatile("ldmatrix.sync.aligned.m8n8.x4.shared.b16 {%0,%1,%2,%3}, [%4];"
        : "=r"(r[0]), "=r"(r[1]), "=r"(r[2]), "=r"(r[3]) : "r"(addr));
}
__device__ __forceinline__ void ldsm4t(uint32_t* r, uint32_t addr) {
    asm volatile("ldmatrix.sync.aligned.m8n8.x4.trans.shared.b16 {%0,%1,%2,%3}, [%4];"
        : "=r"(r[0]), "=r"(r[1]), "=r"(r[2]), "=r"(r[3]) : "r"(addr));
}
__device__ __forceinline__ void mma_bf16(float* c, const uint32_t* a, const uint32_t* b) {
    asm volatile("mma.sync.aligned.m16n8k16.row.col.f32.bf16.bf16.f32 "
        "{%0,%1,%2,%3}, {%4,%5,%6,%7}, {%8,%9}, {%0,%1,%2,%3};"
        : "+f"(c[0]), "+f"(c[1]), "+f"(c[2]), "+f"(c[3])
        : "r"(a[0]), "r"(a[1]), "r"(a[2]), "r"(a[3]), "r"(b[0]), "r"(b[1]));
}
__device__ __forceinline__ uint32_t pack2bf16(float a, float b) {
    unsigned short ua = __bfloat16_as_ushort(__float2bfloat16(a));
    unsigned short ub = __bfloat16_as_ushort(__float2bfloat16(b));
    return ((uint32_t)ub << 16) | ua;
}
__device__ __forceinline__ void cp16(uint32_t dst, const void* src) {
    asm volatile("cp.async.cg.shared.global [%0], [%1], 16;" :: "r"(dst), "l"(src));
}
#define CP_COMMIT() asm volatile("cp.async.commit_group;" ::: "memory")
#define CP_WAIT(n)  asm volatile("cp.async.wait_group %0;" :: "n"(n) : "memory")

// ======================= scratch =======================
__device__ float g_pht[H_ * B_];               // [h][b]
__device__ float g_scores[B_ * V_];            // [b][v]
__device__ float g_red2[256];                  // 128 blocks x (sum, sumsq)
// split weights: [mat(2)][split(2)][k(256)][n(256)] bf16
__device__ __align__(16) __nv_bfloat16 g_Bs[2 * 2 * 256 * 256];

// ---------------- prep: blocks 0..127 weight split, 128..143 patient ----------------
__global__ __launch_bounds__(1024)
void k_prep(const float* __restrict__ Wa, const float* __restrict__ W1,
            const float* __restrict__ pe, const float* __restrict__ Wp,
            const float* __restrict__ bp, const float* __restrict__ gp,
            const float* __restrict__ betap, const float* __restrict__ b1)
{
    int tid = threadIdx.x;
    if (blockIdx.x < 128) {
        int e = blockIdx.x * 1024 + tid;
        int mat = e >> 16;
        int rem = e & 65535;
        const float* W = mat ? (W1 + (size_t)D_ * H_) : Wa;
        float v = W[rem];
        __nv_bfloat16 h = __float2bfloat16(v);
        g_Bs[(size_t)(mat * 2 + 0) * 65536 + rem] = h;
        g_Bs[(size_t)(mat * 2 + 1) * 65536 + rem] = __float2bfloat16(v - __bfloat162float(h));
        return;
    }
    int b = blockIdx.x - 128;
    int d = tid & 255;
    int q = tid >> 8;
    __shared__ float s_pe[D_], s_p[D_];
    __shared__ float red[4][D_];
    __shared__ float r1[8], r2[8], bc[2];
    if (tid < 256) s_pe[tid] = pe[b * D_ + tid];
    __syncthreads();

    float part = 0.f;
    {
        const float* Wq = Wp + (size_t)(q * 64) * 256 + d;
        #pragma unroll 16
        for (int kk = 0; kk < 64; kk++)
            part = fmaf(s_pe[q * 64 + kk], Wq[(size_t)kk * 256], part);
    }
    red[q][d] = part;
    __syncthreads();

    float acc = 0.f;
    if (tid < 256) {
        acc = red[0][d] + red[1][d] + red[2][d] + red[3][d] + bp[d];
        float s1 = acc, s2 = acc * acc;
        #pragma unroll
        for (int o = 16; o; o >>= 1) {
            s1 += __shfl_xor_sync(0xffffffffu, s1, o);
            s2 += __shfl_xor_sync(0xffffffffu, s2, o);
        }
        if ((tid & 31) == 0) { r1[tid >> 5] = s1; r2[tid >> 5] = s2; }
    }
    __syncthreads();
    if (tid == 0) {
        float t1 = 0.f, t2 = 0.f;
        #pragma unroll
        for (int i = 0; i < 8; i++) { t1 += r1[i]; t2 += r2[i]; }
        float mean = t1 * (1.0f / D_);
        float var  = t2 * (1.0f / D_) - mean * mean;
        bc[0] = mean; bc[1] = rsqrtf(var + EPS_);
    }
    __syncthreads();
    if (tid < 256) s_p[d] = (acc - bc[0]) * bc[1] * gp[d] + betap[d];
    __syncthreads();

    float part2 = 0.f;
    {
        const float* W1q = W1 + (size_t)(q * 64) * 256 + d;
        #pragma unroll 16
        for (int kk = 0; kk < 64; kk++)
            part2 = fmaf(s_p[q * 64 + kk], W1q[(size_t)kk * 256], part2);
    }
    red[q][d] = part2;
    __syncthreads();
    if (tid < 256)
        g_pht[d * B_ + b] = red[0][d] + red[1][d] + red[2][d] + red[3][d] + b1[d];
}

// ---------------- fused HMMA + LN + score kernel ----------------
// 3 B slots (interleaved hi|lo rows of 1040B), ONE barrier per chunk,
// cp.async issued at bottom (after mma). Stats overlay dead slot 0 at t==15.
static constexpr uint32_t A_HI   = 0;
static constexpr uint32_t A_LO   = 32768;
static constexpr uint32_t B_B0   = 65536;
static constexpr uint32_t B_STR  = 16640;     // 16 rows x 1040B per slot
static constexpr uint32_t SMEM_SZ = 115456;   // 65536 + 3*16640
// LN-stat overlays inside dead slot 0 during t==15 epilogue:
static constexpr uint32_t SO_PS = B_B0;           // 256 floats
static constexpr uint32_t SO_PQ = B_B0 + 1024;    // 256 floats
static constexpr uint32_t SO_MR = B_B0 + 2048;    // 128 floats
// score-epilogue overlays (A region dead after chunk 31):
static constexpr uint32_t S2_AH  = 0;
static constexpr uint32_t S2_PHT = 34816;
static constexpr uint32_t S2_W2  = 44032;

__global__ __launch_bounds__(256, 2)
void k_fused(const float* __restrict__ atc4,
             const float* __restrict__ ba,
             const float* __restrict__ ga,
             const float* __restrict__ betaa,
             const float* __restrict__ W2,
             const float* __restrict__ b2)
{
    extern __shared__ __align__(16) unsigned char smem[];
    uint32_t sb = smem_u32(smem);
    int tid = threadIdx.x;
    int wid = tid >> 5;
    int l   = tid & 31;
    int wm  = wid >> 2;
    int wn  = wid & 3;
    int quad = l >> 2;
    int tid4 = l & 3;
    int m0 = blockIdx.x * 64;

    auto issue = [&](int t) {
        int phase = t >> 4, c = t & 15;
        uint32_t bb = sb + B_B0 + (uint32_t)(t % 3) * B_STR;
        const __nv_bfloat16* bh = g_Bs + (size_t)(phase * 2) * 65536 + (size_t)c * 16 * 256;
        const __nv_bfloat16* bl = bh + 65536;
        #pragma unroll
        for (int it = 0; it < 2; it++) {
            int id = it * 256 + tid;       // 0..511
            int k = id >> 5, u = id & 31;
            uint32_t dst = bb + (uint32_t)k * 1040 + (uint32_t)u * 16;
            cp16(dst,       bh + (size_t)k * 256 + u * 8);
            cp16(dst + 512, bl + (size_t)k * 256 + u * 8);
        }
        CP_COMMIT();
    };

    issue(0);
    issue(1);

    // ---- convert atc4 tile -> bf16 hi/lo into swizzled A smem ----
    #pragma unroll
    for (int it = 0; it < 8; it++) {
        int id = it * 256 + tid;
        int row = id >> 5, u = id & 31;
        int gr = m0 + row;
        float f[8];
        if (gr < V_) {
            float4 v0 = *(const float4*)&atc4[(size_t)gr * 256 + u * 8];
            float4 v1 = *(const float4*)&atc4[(size_t)gr * 256 + u * 8 + 4];
            f[0]=v0.x; f[1]=v0.y; f[2]=v0.z; f[3]=v0.w;
            f[4]=v1.x; f[5]=v1.y; f[6]=v1.z; f[7]=v1.w;
        } else {
            #pragma unroll
            for (int i = 0; i < 8; i++) f[i] = 0.f;
        }
        float hf[8], lf[8];
        #pragma unroll
        for (int i = 0; i < 8; i++) {
            hf[i] = __bfloat162float(__float2bfloat16(f[i]));
            lf[i] = f[i] - hf[i];
        }
        uint4 hp, lp;
        hp.x = pack2bf16(hf[0], hf[1]); hp.y = pack2bf16(hf[2], hf[3]);
        hp.z = pack2bf16(hf[4], hf[5]); hp.w = pack2bf16(hf[6], hf[7]);
        lp.x = pack2bf16(lf[0], lf[1]); lp.y = pack2bf16(lf[2], lf[3]);
        lp.z = pack2bf16(lf[4], lf[5]); lp.w = pack2bf16(lf[6], lf[7]);
        uint32_t off = (uint32_t)row * 512 + (((uint32_t)u ^ ((uint32_t)row & 7)) << 4);
        *(uint4*)(smem + A_HI + off) = hp;
        *(uint4*)(smem + A_LO + off) = lp;
    }

    int ar = wm * 32 + (l & 15);
    uint32_t arx = (uint32_t)(ar & 7);
    uint32_t a_base = sb + A_HI + (uint32_t)ar * 512;
    uint32_t kusel = (uint32_t)((l >> 4) & 1);
    uint32_t b_lane = (uint32_t)(l & 15) * 1040 + (uint32_t)(wn * 64 + ((l >> 4) & 1) * 8) * 2;

    float acc[8][2][4];
    #pragma unroll
    for (int nb = 0; nb < 8; nb++)
        #pragma unroll
        for (int mb = 0; mb < 2; mb++)
            #pragma unroll
            for (int i = 0; i < 4; i++) acc[nb][mb][i] = 0.f;

    #pragma unroll 1
    for (int t = 0; t < 32; t++) {
        int c = t & 15;
        uint32_t bb = sb + B_B0 + (uint32_t)(t % 3) * B_STR;

        if (t == 31) { CP_WAIT(0); } else { CP_WAIT(1); }
        __syncthreads();           // data visible; slot (t+2)%3 consumed at t-1

        uint32_t ku = (uint32_t)(c * 2) + kusel;
        uint32_t aa = a_base + ((ku ^ arx) << 4);
        uint32_t ah0[4], ah1[4], al0[4], al1[4];
        ldsm4(ah0, aa);
        ldsm4(ah1, aa + 8192);
        ldsm4(al0, aa + 32768);
        ldsm4(al1, aa + 40960);
        #pragma unroll
        for (int p = 0; p < 4; p++) {
            uint32_t bo = bb + b_lane + (uint32_t)(p * 32);
            uint32_t rh[4], rl[4];
            ldsm4t(rh, bo);
            ldsm4t(rl, bo + 512);
            #pragma unroll
            for (int q = 0; q < 2; q++) {
                int nb = p * 2 + q;
                mma_bf16(acc[nb][0], ah0, &rh[q * 2]);
                mma_bf16(acc[nb][0], ah0, &rl[q * 2]);
                mma_bf16(acc[nb][0], al0, &rh[q * 2]);
                mma_bf16(acc[nb][1], ah1, &rh[q * 2]);
                mma_bf16(acc[nb][1], ah1, &rl[q * 2]);
                mma_bf16(acc[nb][1], al1, &rh[q * 2]);
            }
        }

        if (t == 15) {
            // slot 2 holds chunk 14 (dead since top-of-15 barrier): prefetch 17 now,
            // overlapping the LN epilogue.
            issue(17);
            __syncthreads();       // all warps' chunk-15 ldsm done -> slot 0 reusable
            float* psum = (float*)(smem + (SO_PS - 0));   // dead slot 0
            float* psq  = (float*)(smem + SO_PQ);
            float* mrs  = (float*)(smem + SO_MR);

            #pragma unroll
            for (int mb = 0; mb < 2; mb++) {
                #pragma unroll
                for (int half = 0; half < 2; half++) {
                    float s1 = 0.f, s2 = 0.f;
                    #pragma unroll
                    for (int nb = 0; nb < 8; nb++) {
                        int col = wn * 64 + nb * 8 + tid4 * 2;
                        float x0 = acc[nb][mb][half * 2 + 0] + __ldg(&ba[col]);
                        float x1 = acc[nb][mb][half * 2 + 1] + __ldg(&ba[col + 1]);
                        s1 += x0 + x1;
                        s2 = fmaf(x0, x0, fmaf(x1, x1, s2));
                    }
                    s1 += __shfl_xor_sync(0xffffffffu, s1, 1);
                    s2 += __shfl_xor_sync(0xffffffffu, s2, 1);
                    s1 += __shfl_xor_sync(0xffffffffu, s1, 2);
                    s2 += __shfl_xor_sync(0xffffffffu, s2, 2);
                    if (tid4 == 0) {
                        int row = wm * 32 + mb * 16 + quad + half * 8;
                        psum[row * 4 + wn] = s1;
                        psq[row * 4 + wn]  = s2;
                    }
                }
            }
            __syncthreads();
            if (tid < 64) {
                float s1 = psum[tid * 4] + psum[tid * 4 + 1] + psum[tid * 4 + 2] + psum[tid * 4 + 3];
                float s2 = psq[tid * 4] + psq[tid * 4 + 1] + psq[tid * 4 + 2] + psq[tid * 4 + 3];
                float mean = s1 * (1.0f / 256.0f);
                float var  = s2 * (1.0f / 256.0f) - mean * mean;
                mrs[tid * 2]     = mean;
                mrs[tid * 2 + 1] = rsqrtf(var + EPS_);
            }
            __syncthreads();
            #pragma unroll
            for (int mb = 0; mb < 2; mb++) {
                #pragma unroll
                for (int half = 0; half < 2; half++) {
                    int row = wm * 32 + mb * 16 + quad + half * 8;
                    float mean = mrs[row * 2], rstd = mrs[row * 2 + 1];
                    #pragma unroll
                    for (int nb = 0; nb < 8; nb++) {
                        int col = wn * 64 + nb * 8 + tid4 * 2;
                        float x0 = acc[nb][mb][half * 2 + 0] + __ldg(&ba[col]);
                        float x1 = acc[nb][mb][half * 2 + 1] + __ldg(&ba[col + 1]);
                        float v0 = (x0 - mean) * rstd * __ldg(&ga[col])     + __ldg(&betaa[col]);
                        float v1 = (x1 - mean) * rstd * __ldg(&ga[col + 1]) + __ldg(&betaa[col + 1]);
                        float h0 = __bfloat162float(__float2bfloat16(v0));
                        float h1 = __bfloat162float(__float2bfloat16(v1));
                        uint32_t u = (uint32_t)(col >> 3);
                        uint32_t off = (uint32_t)row * 512 + ((u ^ ((uint32_t)row & 7)) << 4)
                                     + (uint32_t)tid4 * 4;
                        *(uint32_t*)(smem + A_HI + off) = pack2bf16(h0, h1);
                        *(uint32_t*)(smem + A_LO + off) = pack2bf16(v0 - h0, v1 - h1);
                    }
                }
            }
            #pragma unroll
            for (int nb = 0; nb < 8; nb++)
                #pragma unroll
                for (int mb = 0; mb < 2; mb++)
                    #pragma unroll
                    for (int i = 0; i < 4; i++) acc[nb][mb][i] = 0.f;
            __syncthreads();       // A rewrite + stats dead before chunk 16
        } else if (t < 30) {
            issue(t + 2);          // slot (t+2)%3, consumed at t-1, safe post top-sync
        }
    }

    // ================= score epilogue (A region is dead) =================
    #pragma unroll
    for (int mb = 0; mb < 2; mb++) {
        #pragma unroll
        for (int half = 0; half < 2; half++) {
            int row = wm * 32 + mb * 16 + quad + half * 8;
            #pragma unroll
            for (int nb = 0; nb < 8; nb++) {
                int col = wn * 64 + nb * 8 + tid4 * 2;
                __half2 h = __floats2half2_rn(acc[nb][mb][half * 2],
                                              acc[nb][mb][half * 2 + 1]);
                *(uint32_t*)(smem + S2_AH + (uint32_t)row * 516 + (uint32_t)(col >> 1) * 4)
                    = *(uint32_t*)&h;
            }
        }
    }
    {
        #pragma unroll
        for (int e = tid; e < 2048; e += 256) {
            int h = e >> 3, b2i = e & 7;
            __half2 p = __floats2half2_rn(g_pht[h * 16 + 2 * b2i], g_pht[h * 16 + 2 * b2i + 1]);
            *(uint32_t*)(smem + S2_PHT + (uint32_t)h * 36 + (uint32_t)b2i * 4) = *(uint32_t*)&p;
        }
        ((float*)(smem + S2_W2))[tid] = W2[tid];
    }
    __syncthreads();

    {
        int r  = tid >> 2;
        int bq = tid & 3;
        const float* s_w2f = (const float*)(smem + S2_W2);
        float part0 = 0.f, part1 = 0.f, part2 = 0.f, part3 = 0.f;
        uint32_t ah_base  = sb + S2_AH + (uint32_t)r * 516;
        uint32_t pht_base = sb + S2_PHT + (uint32_t)bq * 8;

        #pragma unroll 4
        for (int h2 = 0; h2 < 128; h2++) {
            uint32_t a2;
            asm("ld.shared.b32 %0, [%1];" : "=r"(a2) : "r"(ah_base + h2 * 4));
            uint32_t blo, bhi;
            asm("prmt.b32 %0, %1, %1, 0x1010;" : "=r"(blo) : "r"(a2));
            asm("prmt.b32 %0, %1, %1, 0x3232;" : "=r"(bhi) : "r"(a2));
            uint32_t p00, p01, p10, p11;
            uint32_t pa = pht_base + (uint32_t)(2 * h2) * 36;
            asm("ld.shared.b32 %0, [%1];" : "=r"(p00) : "r"(pa));
            asm("ld.shared.b32 %0, [%1];" : "=r"(p01) : "r"(pa + 4));
            asm("ld.shared.b32 %0, [%1];" : "=r"(p10) : "r"(pa + 36));
            asm("ld.shared.b32 %0, [%1];" : "=r"(p11) : "r"(pa + 40));
            uint32_t x00, x01, x10, x11;
            asm("add.rn.f16x2 %0, %1, %2;" : "=r"(x00) : "r"(blo), "r"(p00));
            asm("add.rn.f16x2 %0, %1, %2;" : "=r"(x01) : "r"(blo), "r"(p01));
            asm("add.rn.f16x2 %0, %1, %2;" : "=r"(x10) : "r"(bhi), "r"(p10));
            asm("add.rn.f16x2 %0, %1, %2;" : "=r"(x11) : "r"(bhi), "r"(p11));
            asm("tanh.approx.f16x2 %0, %1;" : "=r"(x00) : "r"(x00));
            asm("tanh.approx.f16x2 %0, %1;" : "=r"(x01) : "r"(x01));
            asm("tanh.approx.f16x2 %0, %1;" : "=r"(x10) : "r"(x10));
            asm("tanh.approx.f16x2 %0, %1;" : "=r"(x11) : "r"(x11));
            float w0 = s_w2f[2 * h2];
            float w1 = s_w2f[2 * h2 + 1];
            float2 f00 = __half22float2(*(__half2*)&x00);
            float2 f01 = __half22float2(*(__half2*)&x01);
            float2 f10 = __half22float2(*(__half2*)&x10);
            float2 f11 = __half22float2(*(__half2*)&x11);
            part0 = fmaf(w0, f00.x, part0); part0 = fmaf(w1, f10.x, part0);
            part1 = fmaf(w0, f00.y, part1); part1 = fmaf(w1, f10.y, part1);
            part2 = fmaf(w0, f01.x, part2); part2 = fmaf(w1, f11.x, part2);
            part3 = fmaf(w0, f01.y, part3); part3 = fmaf(w1, f11.y, part3);
        }
        int grow = m0 + r;
        if (grow < V_) {
            float b2v = b2[0];
            g_scores[(size_t)(4 * bq + 0) * V_ + grow] = part0 + b2v;
            g_scores[(size_t)(4 * bq + 1) * V_ + grow] = part1 + b2v;
            g_scores[(size_t)(4 * bq + 2) * V_ + grow] = part2 + b2v;
            g_scores[(size_t)(4 * bq + 3) * V_ + grow] = part3 + b2v;
        }
    }
}

// ---------------- LN over V, stage 1: partial sums (128 blocks) ----------------
__global__ __launch_bounds__(256)
void k_red()
{
    int bx = blockIdx.x;            // 0..127
    int b = bx >> 3, s = bx & 7;
    const float4* row = (const float4*)&g_scores[(size_t)b * V_];
    int base = s * 625;             // V/4 = 5000 = 8*625
    float s1 = 0.f, s2 = 0.f;
    for (int i = threadIdx.x; i < 625; i += 256) {
        float4 x = row[base + i];
        s1 += x.x + x.y + x.z + x.w;
        s2 = fmaf(x.x, x.x, fmaf(x.y, x.y, fmaf(x.z, x.z, fmaf(x.w, x.w, s2))));
    }
    #pragma unroll
    for (int o = 16; o; o >>= 1) {
        s1 += __shfl_xor_sync(0xffffffffu, s1, o);
        s2 += __shfl_xor_sync(0xffffffffu, s2, o);
    }
    __shared__ float r1[8], r2[8];
    int w = threadIdx.x >> 5, ll = threadIdx.x & 31;
    if (ll == 0) { r1[w] = s1; r2[w] = s2; }
    __syncthreads();
    if (threadIdx.x == 0) {
        float t1 = 0.f, t2 = 0.f;
        #pragma unroll
        for (int i = 0; i < 8; i++) { t1 += r1[i]; t2 += r2[i]; }
        g_red2[bx * 2]     = t1;
        g_red2[bx * 2 + 1] = t2;
    }
}

// ---------------- LN over V, stage 2: normalize (128 blocks) ----------------
__global__ __launch_bounds__(256)
void k_norm(const float* __restrict__ g_pred,
            const float* __restrict__ b_pred,
            float* __restrict__ out)
{
    int bx = blockIdx.x;
    int b = bx >> 3, s = bx & 7;
    float t1 = 0.f, t2 = 0.f;
    #pragma unroll
    for (int i = 0; i < 8; i++) {
        t1 += g_red2[(b * 8 + i) * 2];
        t2 += g_red2[(b * 8 + i) * 2 + 1];
    }
    float mean = t1 * (1.0f / V_);
    float var  = t2 * (1.0f / V_) - mean * mean;
    float rstd = rsqrtf(var + EPS_);

    const float4* row = (const float4*)&g_scores[(size_t)b * V_];
    const float4* gp4 = (const float4*)g_pred;
    const float4* bp4 = (const float4*)b_pred;
    float4* out4 = (float4*)&out[(size_t)b * V_];
    int base = s * 625;
    for (int i = threadIdx.x; i < 625; i += 256) {
        float4 x = row[base + i];
        float4 g = gp4[base + i];
        float4 be = bp4[base + i];
        float4 o;
        o.x = (x.x - mean) * rstd * g.x + be.x;
        o.y = (x.y - mean) * rstd * g.y + be.y;
        o.z = (x.z - mean) * rstd * g.z + be.z;
        o.w = (x.w - mean) * rstd * g.w + be.w;
        out4[base + i] = o;
    }
}

// ---------------- launch ----------------
extern "C" void kernel_launch(void* const* d_in, const int* in_sizes, int n_in,
                              void* d_out, int out_size)
{
    const float* pe     = (const float*)d_in[0];
    const float* atc4   = (const float*)d_in[1];
    const float* Wp     = (const float*)d_in[2];
    const float* bp     = (const float*)d_in[3];
    const float* gp     = (const float*)d_in[4];
    const float* betap  = (const float*)d_in[5];
    const float* Wa     = (const float*)d_in[6];
    const float* ba     = (const float*)d_in[7];
    const float* ga     = (const float*)d_in[8];
    const float* betaa  = (const float*)d_in[9];
    const float* W1     = (const float*)d_in[10];
    const float* b1     = (const float*)d_in[11];
    const float* W2     = (const float*)d_in[12];
    const float* b2     = (const float*)d_in[13];
    const float* gpred  = (const float*)d_in[14];
    const float* bpred  = (const float*)d_in[15];
    float* out = (float*)d_out;
    (void)in_sizes; (void)n_in; (void)out_size;

    cudaFuncSetAttribute(k_fused, cudaFuncAttributeMaxDynamicSharedMemorySize, SMEM_SZ);

    k_prep<<<144, 1024>>>(Wa, W1, pe, Wp, bp, gp, betap, b1);

    int tiles = (V_ + 63) / 64;   // 313
    k_fused<<<tiles, 256, SMEM_SZ>>>(atc4, ba, ga, betaa, W2, b2);

    k_red<<<128, 256>>>();
    k_norm<<<128, 256>>>(gpred, bpred, out);
}